// round 7
// baseline (speedup 1.0000x reference)
#include <cuda_runtime.h>
#include <cuda_bf16.h>
#include <cstdint>

#define BB 8
#define NN 8192
#define DD 256
#define NSPLIT 16
#define TOTROWS (BB*NN)    // 65536

// ---------------- scratch globals ------------------------------------------
__device__ __nv_bfloat16 g_Fhi[TOTROWS*DD];
__device__ __nv_bfloat16 g_Flo[TOTROWS*DD];
__device__ __nv_bfloat16 g_Qhi[TOTROWS*DD];
__device__ __nv_bfloat16 g_Qlo[TOTROWS*DD];
__device__ __nv_bfloat16 g_Wthi[768*DD];
__device__ __nv_bfloat16 g_Wtlo[768*DD];
__device__ __nv_bfloat16 g_Kthi[BB*DD*NN];        // K logits transposed [b][d][n]
__device__ __nv_bfloat16 g_Ktlo[BB*DD*NN];
__device__ __nv_bfloat16 g_Pthi[BB*DD*NN];        // P transposed [b][d][n]
__device__ __nv_bfloat16 g_Ptlo[BB*DD*NN];
__device__ __nv_bfloat16 g_Vthi[BB*DD*NN];        // V transposed [b][e][n]
__device__ __nv_bfloat16 g_Vtlo[BB*DD*NN];
__device__ __nv_bfloat16 g_bnThi[BB*DD*DD];       // bn transposed [b][e][d]
__device__ __nv_bfloat16 g_bnTlo[BB*DD*DD];
__device__ float g_lampart[NSPLIT*BB*DD*DD];
__device__ float g_lam[BB*DD*DD];
__device__ float g_scale[DD];
__device__ float g_shift[DD];

// ---------------- helpers --------------------------------------------------
__device__ __forceinline__ uint32_t smem_to_u32(const void* p) {
    uint32_t a;
    asm("{ .reg .u64 t; cvta.to.shared.u64 t, %1; cvt.u32.u64 %0, t; }" : "=r"(a) : "l"(p));
    return a;
}
#define LDSM4(R, addr) \
    asm volatile("ldmatrix.sync.aligned.m8n8.x4.shared.b16 {%0,%1,%2,%3}, [%4];" \
        : "=r"((R)[0]), "=r"((R)[1]), "=r"((R)[2]), "=r"((R)[3]) : "r"(addr))
#define LDSM2(R, addr) \
    asm volatile("ldmatrix.sync.aligned.m8n8.x2.shared.b16 {%0,%1}, [%2];" \
        : "=r"((R)[0]), "=r"((R)[1]) : "r"(addr))
#define CP16(smaddr, gptr) \
    asm volatile("cp.async.cg.shared.global [%0], [%1], 16;" \
        :: "r"((uint32_t)(smaddr)), "l"(gptr))
#define CP_COMMIT() asm volatile("cp.async.commit_group;" ::: "memory")
#define CP_WAIT1()  asm volatile("cp.async.wait_group 1;" ::: "memory")
#define CP_WAIT0()  asm volatile("cp.async.wait_group 0;" ::: "memory")

__device__ __forceinline__ void mma_bf16(float* c, const uint32_t* a, const uint32_t* b) {
    asm volatile("mma.sync.aligned.m16n8k16.row.col.f32.bf16.bf16.f32 "
        "{%0,%1,%2,%3}, {%4,%5,%6,%7}, {%8,%9}, {%0,%1,%2,%3};"
        : "+f"(c[0]), "+f"(c[1]), "+f"(c[2]), "+f"(c[3])
        : "r"(a[0]), "r"(a[1]), "r"(a[2]), "r"(a[3]), "r"(b[0]), "r"(b[1]));
}

__device__ __forceinline__ float fexp(float x) {
    float y = x * 1.4426950408889634f;
    y = fmaxf(y, -126.0f);
    float r = rintf(y);
    float t = (y - r) * 0.6931471805599453f;
    float p = 1.3888889e-3f;
    p = fmaf(p, t, 8.3333333e-3f);
    p = fmaf(p, t, 4.1666667e-2f);
    p = fmaf(p, t, 1.6666667e-1f);
    p = fmaf(p, t, 0.5f);
    p = fmaf(p, t, 1.0f);
    p = fmaf(p, t, 1.0f);
    float sc = __int_as_float(((int)r + 127) << 23);
    return p * sc;
}
__device__ __forceinline__ void split2(float v, __nv_bfloat16& h, __nv_bfloat16& l) {
    h = __float2bfloat16(v);
    l = __float2bfloat16(v - __bfloat162float(h));
}

// ---------------- feature split --------------------------------------------
__global__ __launch_bounds__(256) void k_split(const float* __restrict__ X)
{
    int t = blockIdx.x * 256 + threadIdx.x;
    float4 v = *(const float4*)&X[t * 4];
    __nv_bfloat16 h[4], l[4];
    split2(v.x, h[0], l[0]); split2(v.y, h[1], l[1]);
    split2(v.z, h[2], l[2]); split2(v.w, h[3], l[3]);
    *(uint2*)&g_Fhi[t * 4] = *(uint2*)h;
    *(uint2*)&g_Flo[t * 4] = *(uint2*)l;
}

// ---------------- W transpose + split --------------------------------------
__global__ __launch_bounds__(256) void k_wsplit(const float* __restrict__ Wqk,
                                               const float* __restrict__ Wv)
{
    int n = blockIdx.x;
    int k = threadIdx.x;
    int sec = n >> 8, nn = n & 255;
    float w = (sec == 0) ? Wqk[k * 256 + nn]
            : (sec == 1) ? Wqk[65536 + k * 256 + nn]
                         : Wv[k * 256 + nn];
    __nv_bfloat16 h, l; split2(w, h, l);
    g_Wthi[n * 256 + k] = h;
    g_Wtlo[n * 256 + k] = l;
}

// ---------------- shared MMA GEMM kernel (cp.async double-buffered) --------
// mode 0: C[65536x768] = F @ Wt^T -> Q row-major split; K,V transposed split
// mode 1: C[65536x256] = Q @ bnT^T -> fp32 out
// mode 2: lam partials: C[256x256] = Pt @ Vt^T over 512-seq split
#define ROWB 80
#define BUFB (128*ROWB)          // 10240 bytes per operand buffer
#define STAGEB (4*BUFB)          // 40960 bytes per stage
#define SMEM_MMA (2*STAGEB)      // 81920 bytes (>= 128*129*4 epilogue staging)

__global__ __launch_bounds__(256) void k_mma(int mode, const float* __restrict__ bqk,
                                             const float* __restrict__ bv,
                                             float* __restrict__ outp)
{
    extern __shared__ __align__(16) unsigned char sm[];
    int tid = threadIdx.x, lane = tid & 31, wid = tid >> 5;
    int wm = wid >> 2, wn = wid & 3;

    const __nv_bfloat16 *Ah, *Al, *Bh, *Bl;
    long astr, bstr;
    int m0, ncol0;
    int nk = (mode == 2) ? 16 : 8;
    if (mode == 0) {
        ncol0 = blockIdx.x * 128; m0 = blockIdx.y * 128;
        Ah = g_Fhi + (long)m0 * 256;  Al = g_Flo + (long)m0 * 256;
        Bh = g_Wthi + (long)ncol0 * 256; Bl = g_Wtlo + (long)ncol0 * 256;
        astr = bstr = 256;
    } else if (mode == 1) {
        ncol0 = blockIdx.x * 128; m0 = blockIdx.y * 128;
        int b = m0 >> 13;
        Ah = g_Qhi + (long)m0 * 256;  Al = g_Qlo + (long)m0 * 256;
        Bh = g_bnThi + (long)b * 65536 + (long)ncol0 * 256;
        Bl = g_bnTlo + (long)b * 65536 + (long)ncol0 * 256;
        astr = bstr = 256;
    } else {
        int e0 = blockIdx.x * 128, d0 = blockIdx.y * 128;
        int b = blockIdx.z >> 4, sp = blockIdx.z & 15;
        long ab = (long)(b * 256 + d0) * NN + sp * 512;
        long bb = (long)(b * 256 + e0) * NN + sp * 512;
        Ah = g_Pthi + ab; Al = g_Ptlo + ab;
        Bh = g_Vthi + bb; Bl = g_Vtlo + bb;
        astr = bstr = NN;
        m0 = d0; ncol0 = e0;
    }

    float c[16][4];
    #pragma unroll
    for (int i = 0; i < 16; i++)
        #pragma unroll
        for (int j = 0; j < 4; j++) c[i][j] = 0.f;

    uint32_t smb = smem_to_u32(sm);
    int lrow0 = tid >> 2, lcc = tid & 3;
    int lrow1 = lrow0 + 64;

    auto load_chunk = [&](int kk, int st) {
        uint32_t sb = smb + st * STAGEB;
        #pragma unroll
        for (int buf = 0; buf < 4; buf++) {
            const __nv_bfloat16* src = (buf == 0) ? Ah : (buf == 1) ? Al
                                     : (buf == 2) ? Bh : Bl;
            long str = (buf < 2) ? astr : bstr;
            CP16(sb + buf * BUFB + lrow0 * ROWB + lcc * 16,
                 src + (long)lrow0 * str + kk + lcc * 8);
            CP16(sb + buf * BUFB + lrow1 * ROWB + lcc * 16,
                 src + (long)lrow1 * str + kk + lcc * 8);
        }
    };

    load_chunk(0, 0);
    CP_COMMIT();

    for (int ch = 0; ch < nk; ch++) {
        int cur = ch & 1;
        if (ch + 1 < nk) { load_chunk((ch + 1) * 32, cur ^ 1); CP_COMMIT(); }
        if (ch + 1 < nk) { CP_WAIT1(); } else { CP_WAIT0(); }
        __syncthreads();

        uint32_t sb = smb + cur * STAGEB;
        #pragma unroll
        for (int k0 = 0; k0 < 2; k0++) {
            uint32_t a_h[4][4], a_l[4][4], b_h[4][2], b_l[4][2];
            #pragma unroll
            for (int mt = 0; mt < 4; mt++) {
                uint32_t ra = sb + (wm*64 + mt*16 + (lane & 15)) * ROWB
                            + (k0*16 + (lane >> 4) * 8) * 2;
                LDSM4(a_h[mt], ra);
                LDSM4(a_l[mt], ra + BUFB);
            }
            #pragma unroll
            for (int nt = 0; nt < 4; nt++) {
                uint32_t rb = sb + 2*BUFB + (wn*32 + nt*8 + (lane & 7)) * ROWB
                            + (k0*16 + ((lane >> 3) & 1) * 8) * 2;
                LDSM2(b_h[nt], rb);
                LDSM2(b_l[nt], rb + BUFB);
            }
            #pragma unroll
            for (int mt = 0; mt < 4; mt++)
                #pragma unroll
                for (int nt = 0; nt < 4; nt++) {
                    mma_bf16(c[mt*4+nt], a_h[mt], b_h[nt]);
                    mma_bf16(c[mt*4+nt], a_h[mt], b_l[nt]);
                    mma_bf16(c[mt*4+nt], a_l[mt], b_h[nt]);
                }
        }
        __syncthreads();
    }

    int rbase = m0 + wm * 64;
    int cl0 = wn * 32;

    if (mode == 0 && (ncol0 >> 8) != 0) {
        // ---- K/V epilogue: bias + transpose + split -> Kt/Vt [b][d][n] ----
        int sec = ncol0 >> 8;
        const float* bb = (sec == 1) ? bqk + 256 : bv;
        int cg0 = ncol0 & 255;
        float* st = (float*)sm;                     // [128 cols][129] staging
        #pragma unroll
        for (int mt = 0; mt < 4; mt++)
            #pragma unroll
            for (int nt = 0; nt < 4; nt++) {
                float* cc = c[mt*4+nt];
                int rl = wm*64 + mt*16 + (lane >> 2);
                int cl = cl0 + nt*8 + (lane & 3)*2;
                float b0 = bb[cg0 + cl], b1 = bb[cg0 + cl + 1];
                st[(cl  )*129 + rl    ] = cc[0] + b0;
                st[(cl+1)*129 + rl    ] = cc[1] + b1;
                st[(cl  )*129 + rl + 8] = cc[2] + b0;
                st[(cl+1)*129 + rl + 8] = cc[3] + b1;
            }
        __syncthreads();
        int j = tid >> 1, seg = tid & 1;            // col j, 64-row half seg
        int bidx = m0 >> 13, noff = m0 & 8191;
        long o = (long)(bidx * 256 + cg0 + j) * NN + noff + seg * 64;
        __nv_bfloat16* dh = ((sec == 1) ? g_Kthi : g_Vthi) + o;
        __nv_bfloat16* dl = ((sec == 1) ? g_Ktlo : g_Vtlo) + o;
        const float* srow = st + j * 129 + seg * 64;
        #pragma unroll
        for (int g8 = 0; g8 < 8; g8++) {
            __nv_bfloat16 hh[8], ll[8];
            #pragma unroll
            for (int i = 0; i < 8; i++) split2(srow[g8*8 + i], hh[i], ll[i]);
            *(uint4*)&dh[g8*8] = *(uint4*)hh;
            *(uint4*)&dl[g8*8] = *(uint4*)ll;
        }
        return;
    }

    // ---- direct epilogues (mode 1, mode 2, mode 0 Q-section) --------------
    #pragma unroll
    for (int mt = 0; mt < 4; mt++) {
        #pragma unroll
        for (int nt = 0; nt < 4; nt++) {
            float* cc = c[mt*4+nt];
            int r0 = rbase + mt*16 + (lane >> 2);
            int cl = cl0 + nt*8 + (lane & 3)*2;
            if (mode == 1) {
                float2 v0 = {cc[0], cc[1]}, v1 = {cc[2], cc[3]};
                *(float2*)&outp[(long)r0 * 256 + ncol0 + cl] = v0;
                *(float2*)&outp[(long)(r0+8) * 256 + ncol0 + cl] = v1;
            } else if (mode == 2) {
                int sp = blockIdx.z & 15;
                int b = blockIdx.z >> 4;
                float* op = g_lampart + (long)sp * (BB*DD*DD) + (long)b * 65536;
                float2 v0 = {cc[0], cc[1]}, v1 = {cc[2], cc[3]};
                *(float2*)&op[(long)r0 * 256 + ncol0 + cl] = v0;
                *(float2*)&op[(long)(r0+8) * 256 + ncol0 + cl] = v1;
            } else {
                int cg = ncol0 + cl;                // Q section: ncol0 < 256
                float b0 = bqk[cg], b1 = bqk[cg+1];
                #pragma unroll
                for (int hrow = 0; hrow < 2; hrow++) {
                    int r = r0 + hrow * 8;
                    float v0 = cc[hrow*2+0] + b0, v1 = cc[hrow*2+1] + b1;
                    __nv_bfloat16 h0,l0,h1,l1;
                    split2(v0,h0,l0); split2(v1,h1,l1);
                    __nv_bfloat162 ph; ph.x = h0; ph.y = h1;
                    __nv_bfloat162 pl; pl.x = l0; pl.y = l1;
                    *(__nv_bfloat162*)&g_Qhi[(long)r*256 + cg] = ph;
                    *(__nv_bfloat162*)&g_Qlo[(long)r*256 + cg] = pl;
                }
            }
        }
    }
}

// ---------------- fused softmax over n: Kt -> Pt ---------------------------
// one block per (b,d) row; 256 threads x 32 elems in registers
__global__ __launch_bounds__(256) void k_softmax()
{
    long bd = blockIdx.x;
    const __nv_bfloat16* kh = g_Kthi + bd * NN;
    const __nv_bfloat16* kl = g_Ktlo + bd * NN;
    __nv_bfloat16* ph = g_Pthi + bd * NN;
    __nv_bfloat16* pl = g_Ptlo + bd * NN;
    int t = threadIdx.x, lane = t & 31, w = t >> 5;

    float x[32];
    #pragma unroll
    for (int k = 0; k < 4; k++) {
        int base = k * 2048 + t * 8;
        uint4 uh = *(const uint4*)&kh[base];
        uint4 ul = *(const uint4*)&kl[base];
        const __nv_bfloat16* hh = (const __nv_bfloat16*)&uh;
        const __nv_bfloat16* ll = (const __nv_bfloat16*)&ul;
        #pragma unroll
        for (int i = 0; i < 8; i++)
            x[k*8+i] = __bfloat162float(hh[i]) + __bfloat162float(ll[i]);
    }
    float m = -1e30f;
    #pragma unroll
    for (int i = 0; i < 32; i++) m = fmaxf(m, x[i]);
    #pragma unroll
    for (int o = 16; o; o >>= 1) m = fmaxf(m, __shfl_xor_sync(0xffffffffu, m, o));
    __shared__ float r1[8], r2[8];
    __shared__ float rbc;
    if (lane == 0) r1[w] = m;
    __syncthreads();
    float M = r1[0];
    #pragma unroll
    for (int i = 1; i < 8; i++) M = fmaxf(M, r1[i]);

    float s = 0.f;
    #pragma unroll
    for (int i = 0; i < 32; i++) { x[i] = fexp(x[i] - M); s += x[i]; }
    #pragma unroll
    for (int o = 16; o; o >>= 1) s += __shfl_xor_sync(0xffffffffu, s, o);
    if (lane == 0) r2[w] = s;
    __syncthreads();
    if (t == 0) {
        float S = 0.f;
        #pragma unroll
        for (int i = 0; i < 8; i++) S += r2[i];
        rbc = 1.0f / S;
    }
    __syncthreads();
    float rcp = rbc;
    #pragma unroll
    for (int k = 0; k < 4; k++) {
        int base = k * 2048 + t * 8;
        __nv_bfloat16 hh[8], ll[8];
        #pragma unroll
        for (int i = 0; i < 8; i++) split2(x[k*8+i] * rcp, hh[i], ll[i]);
        *(uint4*)&ph[base] = *(uint4*)hh;
        *(uint4*)&pl[base] = *(uint4*)ll;
    }
}

// ---------------- reduce split-K -------------------------------------------
__global__ __launch_bounds__(256) void k_red()
{
    int t = blockIdx.x * 256 + threadIdx.x;
    float4 a = make_float4(0.f, 0.f, 0.f, 0.f);
    #pragma unroll
    for (int s = 0; s < NSPLIT; s++) {
        float4 v = *(float4*)&g_lampart[(long)s * (BB*DD*DD) + t * 4];
        a.x += v.x; a.y += v.y; a.z += v.z; a.w += v.w;
    }
    *(float4*)&g_lam[t * 4] = a;
}

// ---------------- BN stats per d -------------------------------------------
__global__ __launch_bounds__(256) void k_bnstat(const float* __restrict__ gamma,
                                               const float* __restrict__ beta)
{
    int d = blockIdx.x;
    int tid = threadIdx.x;
    float sum = 0.f, sq = 0.f;
    #pragma unroll
    for (int i = 0; i < 8; i++) {
        int f = tid + i * 256;
        int b = f >> 8, e = f & 255;
        float v = g_lam[(b * 256 + d) * 256 + e];
        sum += v; sq = fmaf(v, v, sq);
    }
    __shared__ float s1[256], s2[256];
    s1[tid] = sum; s2[tid] = sq;
    __syncthreads();
    for (int st = 128; st > 0; st >>= 1) {
        if (tid < st) { s1[tid] += s1[tid+st]; s2[tid] += s2[tid+st]; }
        __syncthreads();
    }
    if (tid == 0) {
        float mean = s1[0] * (1.0f / 2048.0f);
        float var  = s2[0] * (1.0f / 2048.0f) - mean * mean;
        float rstd = rsqrtf(var + 1e-5f);
        float sc = rstd * gamma[d];
        g_scale[d] = sc;
        g_shift[d] = beta[d] - mean * sc;
    }
}

// ---------------- bnT = transpose(BN(lam)), split --------------------------
__global__ void k_bnT()
{
    __shared__ float tile[32][33];
    int b = blockIdx.z, dt = blockIdx.y * 32, et = blockIdx.x * 32;
    int tx = threadIdx.x, ty = threadIdx.y;
    #pragma unroll
    for (int i = 0; i < 4; i++) {
        int d = dt + ty + i * 8;
        float sc = g_scale[d], sh = g_shift[d];
        tile[ty + i * 8][tx] = fmaf(g_lam[(b * 256 + d) * 256 + et + tx], sc, sh);
    }
    __syncthreads();
    #pragma unroll
    for (int i = 0; i < 4; i++) {
        int e = et + ty + i * 8;
        float v = tile[tx][ty + i * 8];
        int o = (b * 256 + e) * 256 + dt + tx;
        __nv_bfloat16 h, l; split2(v, h, l);
        g_bnThi[o] = h; g_bnTlo[o] = l;
    }
}

// ---------------- launch ---------------------------------------------------
extern "C" void kernel_launch(void* const* d_in, const int* in_sizes, int n_in,
                              void* d_out, int out_size)
{
    const float* feature = (const float*)d_in[0];
    const float* W_qk    = (const float*)d_in[1];
    const float* b_qk    = (const float*)d_in[2];
    const float* W_v     = (const float*)d_in[3];
    const float* b_v     = (const float*)d_in[4];
    const float* gamma   = (const float*)d_in[5];
    const float* beta    = (const float*)d_in[6];
    float* out = (float*)d_out;

    cudaFuncSetAttribute(k_mma, cudaFuncAttributeMaxDynamicSharedMemorySize,
                         SMEM_MMA);

    k_split<<<16384, 256>>>(feature);
    k_wsplit<<<768, 256>>>(W_qk, W_v);
    k_mma<<<dim3(6, 512), 256, SMEM_MMA>>>(0, b_qk, b_v, nullptr);   // QKV (+T)
    k_softmax<<<BB*DD, 256>>>();                                     // Kt -> Pt
    k_mma<<<dim3(2, 2, BB*NSPLIT), 256, SMEM_MMA>>>(2, nullptr, nullptr, nullptr);
    k_red<<<512, 256>>>();
    k_bnstat<<<256, 256>>>(gamma, beta);
    k_bnT<<<dim3(8, 8, 8), dim3(32, 8)>>>();
    k_mma<<<dim3(2, 512), 256, SMEM_MMA>>>(1, nullptr, nullptr, out);
}

// round 8
// speedup vs baseline: 1.4562x; 1.4562x over previous
#include <cuda_runtime.h>
#include <cuda_bf16.h>
#include <cstdint>

#define BB 8
#define NN 8192
#define DD 256
#define NSPLIT 8
#define NCHUNK 32          // k_stats row chunks (8192/256)
#define TOTROWS (BB*NN)    // 65536

// ---------------- scratch globals ------------------------------------------
__device__ float g_K[TOTROWS*DD];                 // fp32 K logits
__device__ float g_V[TOTROWS*DD];                 // fp32 V
__device__ __nv_bfloat16 g_Fhi[TOTROWS*DD];
__device__ __nv_bfloat16 g_Flo[TOTROWS*DD];
__device__ __nv_bfloat16 g_Qhi[TOTROWS*DD];
__device__ __nv_bfloat16 g_Qlo[TOTROWS*DD];
__device__ __nv_bfloat16 g_Wthi[768*DD];
__device__ __nv_bfloat16 g_Wtlo[768*DD];
__device__ __nv_bfloat16 g_Pthi[BB*DD*NN];        // P transposed [b][d][n]
__device__ __nv_bfloat16 g_Ptlo[BB*DD*NN];
__device__ __nv_bfloat16 g_Vthi[BB*DD*NN];        // V transposed [b][e][n]
__device__ __nv_bfloat16 g_Vtlo[BB*DD*NN];
__device__ __nv_bfloat16 g_bnThi[BB*DD*DD];       // bn transposed [b][e][d]
__device__ __nv_bfloat16 g_bnTlo[BB*DD*DD];
__device__ float g_pmax[NCHUNK*BB*DD];
__device__ float g_psum[NCHUNK*BB*DD];
__device__ float g_colmax[BB*DD];
__device__ float g_colrcp[BB*DD];
__device__ float g_lampart[NSPLIT*BB*DD*DD];
__device__ float g_lam[BB*DD*DD];
__device__ float g_scale[DD];
__device__ float g_shift[DD];

// ---------------- helpers --------------------------------------------------
__device__ __forceinline__ uint32_t smem_to_u32(const void* p) {
    uint32_t a;
    asm("{ .reg .u64 t; cvta.to.shared.u64 t, %1; cvt.u32.u64 %0, t; }" : "=r"(a) : "l"(p));
    return a;
}
#define LDSM4(R, addr) \
    asm volatile("ldmatrix.sync.aligned.m8n8.x4.shared.b16 {%0,%1,%2,%3}, [%4];" \
        : "=r"((R)[0]), "=r"((R)[1]), "=r"((R)[2]), "=r"((R)[3]) : "r"(addr))
#define LDSM2(R, addr) \
    asm volatile("ldmatrix.sync.aligned.m8n8.x2.shared.b16 {%0,%1}, [%2];" \
        : "=r"((R)[0]), "=r"((R)[1]) : "r"(addr))
#define CP16(smaddr, gptr) \
    asm volatile("cp.async.cg.shared.global [%0], [%1], 16;" \
        :: "r"((uint32_t)(smaddr)), "l"(gptr))
#define CP_COMMIT() asm volatile("cp.async.commit_group;" ::: "memory")
#define CP_WAIT1()  asm volatile("cp.async.wait_group 1;" ::: "memory")
#define CP_WAIT0()  asm volatile("cp.async.wait_group 0;" ::: "memory")

__device__ __forceinline__ void mma_bf16(float* c, const uint32_t* a, const uint32_t* b) {
    asm volatile("mma.sync.aligned.m16n8k16.row.col.f32.bf16.bf16.f32 "
        "{%0,%1,%2,%3}, {%4,%5,%6,%7}, {%8,%9}, {%0,%1,%2,%3};"
        : "+f"(c[0]), "+f"(c[1]), "+f"(c[2]), "+f"(c[3])
        : "r"(a[0]), "r"(a[1]), "r"(a[2]), "r"(a[3]), "r"(b[0]), "r"(b[1]));
}

__device__ __forceinline__ float fexp(float x) {
    float y = x * 1.4426950408889634f;
    y = fmaxf(y, -126.0f);
    float r = rintf(y);
    float t = (y - r) * 0.6931471805599453f;
    float p = 1.3888889e-3f;
    p = fmaf(p, t, 8.3333333e-3f);
    p = fmaf(p, t, 4.1666667e-2f);
    p = fmaf(p, t, 1.6666667e-1f);
    p = fmaf(p, t, 0.5f);
    p = fmaf(p, t, 1.0f);
    p = fmaf(p, t, 1.0f);
    float sc = __int_as_float(((int)r + 127) << 23);
    return p * sc;
}
__device__ __forceinline__ void split2(float v, __nv_bfloat16& h, __nv_bfloat16& l) {
    h = __float2bfloat16(v);
    l = __float2bfloat16(v - __bfloat162float(h));
}

// ---------------- feature split --------------------------------------------
__global__ __launch_bounds__(256) void k_split(const float* __restrict__ X)
{
    int t = blockIdx.x * 256 + threadIdx.x;
    float4 v = *(const float4*)&X[t * 4];
    __nv_bfloat16 h[4], l[4];
    split2(v.x, h[0], l[0]); split2(v.y, h[1], l[1]);
    split2(v.z, h[2], l[2]); split2(v.w, h[3], l[3]);
    *(uint2*)&g_Fhi[t * 4] = *(uint2*)h;
    *(uint2*)&g_Flo[t * 4] = *(uint2*)l;
}

// ---------------- W transpose + split --------------------------------------
__global__ __launch_bounds__(256) void k_wsplit(const float* __restrict__ Wqk,
                                               const float* __restrict__ Wv)
{
    int n = blockIdx.x;
    int k = threadIdx.x;
    int sec = n >> 8, nn = n & 255;
    float w = (sec == 0) ? Wqk[k * 256 + nn]
            : (sec == 1) ? Wqk[65536 + k * 256 + nn]
                         : Wv[k * 256 + nn];
    __nv_bfloat16 h, l; split2(w, h, l);
    g_Wthi[n * 256 + k] = h;
    g_Wtlo[n * 256 + k] = l;
}

// ---------------- shared MMA GEMM kernel (cp.async double-buffered) --------
// mode 0: C[65536x768] = F @ Wt^T  -> scatter Q(split)/K/V (+bias)
// mode 1: C[65536x256] = Q @ bnT^T -> fp32 out
// mode 2: lam partials: C[256x256] = Pt @ Vt^T over 1024-seq split
#define ROWB 80
#define BUFB (128*ROWB)          // 10240 bytes per operand buffer
#define STAGEB (4*BUFB)          // 40960 bytes per stage
#define SMEM_MMA (2*STAGEB)      // 81920 bytes

__global__ __launch_bounds__(256) void k_mma(int mode, const float* __restrict__ bqk,
                                             const float* __restrict__ bv,
                                             float* __restrict__ outp)
{
    extern __shared__ __align__(16) unsigned char sm[];
    int tid = threadIdx.x, lane = tid & 31, wid = tid >> 5;
    int wm = wid >> 2, wn = wid & 3;

    const __nv_bfloat16 *Ah, *Al, *Bh, *Bl;
    long astr, bstr;
    int m0, ncol0;
    int nk = (mode == 2) ? 32 : 8;
    if (mode == 0) {
        ncol0 = blockIdx.x * 128; m0 = blockIdx.y * 128;
        Ah = g_Fhi + (long)m0 * 256;  Al = g_Flo + (long)m0 * 256;
        Bh = g_Wthi + (long)ncol0 * 256; Bl = g_Wtlo + (long)ncol0 * 256;
        astr = bstr = 256;
    } else if (mode == 1) {
        ncol0 = blockIdx.x * 128; m0 = blockIdx.y * 128;
        int b = m0 >> 13;
        Ah = g_Qhi + (long)m0 * 256;  Al = g_Qlo + (long)m0 * 256;
        Bh = g_bnThi + (long)b * 65536 + (long)ncol0 * 256;
        Bl = g_bnTlo + (long)b * 65536 + (long)ncol0 * 256;
        astr = bstr = 256;
    } else {
        int e0 = blockIdx.x * 128, d0 = blockIdx.y * 128;
        int b = blockIdx.z >> 3, sp = blockIdx.z & 7;
        long ab = (long)(b * 256 + d0) * NN + sp * 1024;
        long bb = (long)(b * 256 + e0) * NN + sp * 1024;
        Ah = g_Pthi + ab; Al = g_Ptlo + ab;
        Bh = g_Vthi + bb; Bl = g_Vtlo + bb;
        astr = bstr = NN;
        m0 = d0; ncol0 = e0;
    }

    float c[16][4];
    #pragma unroll
    for (int i = 0; i < 16; i++)
        #pragma unroll
        for (int j = 0; j < 4; j++) c[i][j] = 0.f;

    uint32_t smb = smem_to_u32(sm);
    int lrow0 = tid >> 2, lcc = tid & 3;
    int lrow1 = lrow0 + 64;

    auto load_chunk = [&](int kk, int st) {
        uint32_t sb = smb + st * STAGEB;
        #pragma unroll
        for (int buf = 0; buf < 4; buf++) {
            const __nv_bfloat16* src = (buf == 0) ? Ah : (buf == 1) ? Al
                                     : (buf == 2) ? Bh : Bl;
            long str = (buf < 2) ? astr : bstr;
            CP16(sb + buf * BUFB + lrow0 * ROWB + lcc * 16,
                 src + (long)lrow0 * str + kk + lcc * 8);
            CP16(sb + buf * BUFB + lrow1 * ROWB + lcc * 16,
                 src + (long)lrow1 * str + kk + lcc * 8);
        }
    };

    load_chunk(0, 0);
    CP_COMMIT();

    for (int ch = 0; ch < nk; ch++) {
        int cur = ch & 1;
        if (ch + 1 < nk) { load_chunk((ch + 1) * 32, cur ^ 1); CP_COMMIT(); }
        if (ch + 1 < nk) { CP_WAIT1(); } else { CP_WAIT0(); }
        __syncthreads();

        uint32_t sb = smb + cur * STAGEB;
        #pragma unroll
        for (int k0 = 0; k0 < 2; k0++) {
            uint32_t a_h[4][4], a_l[4][4], b_h[4][2], b_l[4][2];
            #pragma unroll
            for (int mt = 0; mt < 4; mt++) {
                uint32_t ra = sb + (wm*64 + mt*16 + (lane & 15)) * ROWB
                            + (k0*16 + (lane >> 4) * 8) * 2;
                LDSM4(a_h[mt], ra);
                LDSM4(a_l[mt], ra + BUFB);
            }
            #pragma unroll
            for (int nt = 0; nt < 4; nt++) {
                uint32_t rb = sb + 2*BUFB + (wn*32 + nt*8 + (lane & 7)) * ROWB
                            + (k0*16 + ((lane >> 3) & 1) * 8) * 2;
                LDSM2(b_h[nt], rb);
                LDSM2(b_l[nt], rb + BUFB);
            }
            #pragma unroll
            for (int mt = 0; mt < 4; mt++)
                #pragma unroll
                for (int nt = 0; nt < 4; nt++) {
                    mma_bf16(c[mt*4+nt], a_h[mt], b_h[nt]);
                    mma_bf16(c[mt*4+nt], a_h[mt], b_l[nt]);
                    mma_bf16(c[mt*4+nt], a_l[mt], b_h[nt]);
                }
        }
        __syncthreads();
    }

    // epilogue
    int rbase = m0 + wm * 64;
    int cl0 = wn * 32;
    #pragma unroll
    for (int mt = 0; mt < 4; mt++) {
        #pragma unroll
        for (int nt = 0; nt < 4; nt++) {
            float* cc = c[mt*4+nt];
            int r0 = rbase + mt*16 + (lane >> 2);
            int cl = cl0 + nt*8 + (lane & 3)*2;
            if (mode == 1) {
                float2 v0 = {cc[0], cc[1]}, v1 = {cc[2], cc[3]};
                *(float2*)&outp[(long)r0 * 256 + ncol0 + cl] = v0;
                *(float2*)&outp[(long)(r0+8) * 256 + ncol0 + cl] = v1;
            } else if (mode == 2) {
                int sp = blockIdx.z & 7;
                int b = blockIdx.z >> 3;
                float* op = g_lampart + (long)sp * (BB*DD*DD) + (long)b * 65536;
                float2 v0 = {cc[0], cc[1]}, v1 = {cc[2], cc[3]};
                *(float2*)&op[(long)r0 * 256 + ncol0 + cl] = v0;
                *(float2*)&op[(long)(r0+8) * 256 + ncol0 + cl] = v1;
            } else {
                int sec = ncol0 >> 8;
                int cg = (ncol0 & 255) + cl;
                if (sec == 0) {
                    float b0 = bqk[cg], b1 = bqk[cg+1];
                    #pragma unroll
                    for (int hrow = 0; hrow < 2; hrow++) {
                        int r = r0 + hrow * 8;
                        float v0 = cc[hrow*2+0] + b0, v1 = cc[hrow*2+1] + b1;
                        __nv_bfloat16 h0,l0,h1,l1;
                        split2(v0,h0,l0); split2(v1,h1,l1);
                        __nv_bfloat162 ph; ph.x = h0; ph.y = h1;
                        __nv_bfloat162 pl; pl.x = l0; pl.y = l1;
                        *(__nv_bfloat162*)&g_Qhi[(long)r*256 + cg] = ph;
                        *(__nv_bfloat162*)&g_Qlo[(long)r*256 + cg] = pl;
                    }
                } else {
                    const float* bb = (sec == 1) ? bqk + 256 : bv;
                    float* dst = (sec == 1) ? g_K : g_V;
                    float b0 = bb[cg], b1 = bb[cg+1];
                    float2 v0 = {cc[0] + b0, cc[1] + b1};
                    float2 v1 = {cc[2] + b0, cc[3] + b1};
                    *(float2*)&dst[(long)r0 * 256 + cg] = v0;
                    *(float2*)&dst[(long)(r0+8) * 256 + cg] = v1;
                }
            }
        }
    }
}

// ---------------- softmax stats phase A: per-chunk partials ----------------
__global__ __launch_bounds__(256) void k_stats1()
{
    int ch = blockIdx.x;
    int b  = blockIdx.y >> 3;
    int d0 = (blockIdx.y & 7) << 5;
    int dd = threadIdx.x & 31;
    int g  = threadIdx.x >> 5;
    int d  = d0 + dd;
    const float* base = g_K + ((long)b * NN + ch * 256) * 256 + d;

    float m = -1e30f, s = 0.f;
    #pragma unroll 4
    for (int n = g; n < 256; n += 8) {
        float x = base[(long)n * 256];
        float nm = fmaxf(m, x);
        s = fmaf(s, fexp(m - nm), fexp(x - nm));
        m = nm;
    }
    __shared__ float sm[8][32], ss[8][32];
    sm[g][dd] = m; ss[g][dd] = s;
    __syncthreads();
    if (g == 0) {
        float M = sm[0][dd], S = ss[0][dd];
        #pragma unroll
        for (int i = 1; i < 8; i++) {
            float m2 = sm[i][dd], s2 = ss[i][dd];
            float nm = fmaxf(M, m2);
            S = S * fexp(M - nm) + s2 * fexp(m2 - nm);
            M = nm;
        }
        g_pmax[ch * (BB*DD) + b * 256 + d] = M;
        g_psum[ch * (BB*DD) + b * 256 + d] = S;
    }
}

// ---------------- phase B: combine chunk partials --------------------------
__global__ __launch_bounds__(256) void k_stats2()
{
    int t = blockIdx.x * 256 + threadIdx.x;
    if (t >= BB*DD) return;
    float M = g_pmax[t], S = g_psum[t];
    #pragma unroll
    for (int i = 1; i < NCHUNK; i++) {
        float m2 = g_pmax[i * (BB*DD) + t], s2 = g_psum[i * (BB*DD) + t];
        float nm = fmaxf(M, m2);
        S = S * fexp(M - nm) + s2 * fexp(m2 - nm);
        M = nm;
    }
    g_colmax[t] = M;
    g_colrcp[t] = 1.0f / S;
}

// ---------------- P transpose: exp-normalize + split -> Pt[b][d][n] --------
__global__ __launch_bounds__(256) void k_normT()
{
    __shared__ float tile[64][33];
    int b = blockIdx.z, d0 = blockIdx.y * 32, n0 = blockIdx.x * 64;
    int lx = threadIdx.x & 31, ly = threadIdx.x >> 5;
    float mx = g_colmax[b * 256 + d0 + lx];
    float rc = g_colrcp[b * 256 + d0 + lx];
    #pragma unroll
    for (int i = 0; i < 8; i++) {
        int n = ly + i * 8;
        float kv = g_K[((long)b * NN + n0 + n) * 256 + d0 + lx];
        tile[n][lx] = fexp(kv - mx) * rc;
    }
    __syncthreads();
    int sx = threadIdx.x & 63, sy = threadIdx.x >> 6;
    #pragma unroll
    for (int j = 0; j < 8; j++) {
        int dl = sy + j * 4;
        float v = tile[sx][dl];
        __nv_bfloat16 h, l; split2(v, h, l);
        long o = (long)(b * 256 + d0 + dl) * NN + n0 + sx;
        g_Pthi[o] = h; g_Ptlo[o] = l;
    }
}

// ---------------- V transpose + split -> Vt[b][e][n] -----------------------
__global__ __launch_bounds__(256) void k_vT()
{
    __shared__ float tile[64][33];
    int b = blockIdx.z, e0 = blockIdx.y * 32, n0 = blockIdx.x * 64;
    int lx = threadIdx.x & 31, ly = threadIdx.x >> 5;
    #pragma unroll
    for (int i = 0; i < 8; i++) {
        int n = ly + i * 8;
        tile[n][lx] = g_V[((long)b * NN + n0 + n) * 256 + e0 + lx];
    }
    __syncthreads();
    int sx = threadIdx.x & 63, sy = threadIdx.x >> 6;
    #pragma unroll
    for (int j = 0; j < 8; j++) {
        int el = sy + j * 4;
        float v = tile[sx][el];
        __nv_bfloat16 h, l; split2(v, h, l);
        long o = (long)(b * 256 + e0 + el) * NN + n0 + sx;
        g_Vthi[o] = h; g_Vtlo[o] = l;
    }
}

// ---------------- fused reduce split-K + BN stats (per d) ------------------
__global__ __launch_bounds__(256) void k_redstat(const float* __restrict__ gamma,
                                                const float* __restrict__ beta)
{
    int d = blockIdx.x;
    int tid = threadIdx.x;
    float sum = 0.f, sq = 0.f;
    #pragma unroll
    for (int i = 0; i < 8; i++) {
        int f = tid + i * 256;       // 0..2047 -> (b, e)
        int b = f >> 8, e = f & 255;
        long idx = ((long)(b * 256 + d)) * 256 + e;
        float v = 0.f;
        #pragma unroll
        for (int s = 0; s < NSPLIT; s++)
            v += g_lampart[(long)s * (BB*DD*DD) + idx];
        g_lam[idx] = v;
        sum += v; sq = fmaf(v, v, sq);
    }
    __shared__ float s1[256], s2[256];
    s1[tid] = sum; s2[tid] = sq;
    __syncthreads();
    for (int st = 128; st > 0; st >>= 1) {
        if (tid < st) { s1[tid] += s1[tid+st]; s2[tid] += s2[tid+st]; }
        __syncthreads();
    }
    if (tid == 0) {
        float mean = s1[0] * (1.0f / 2048.0f);
        float var  = s2[0] * (1.0f / 2048.0f) - mean * mean;
        float rstd = rsqrtf(var + 1e-5f);
        float sc = rstd * gamma[d];
        g_scale[d] = sc;
        g_shift[d] = beta[d] - mean * sc;
    }
}

// ---------------- bnT = transpose(BN(lam)), split --------------------------
__global__ void k_bnT()
{
    __shared__ float tile[32][33];
    int b = blockIdx.z, dt = blockIdx.y * 32, et = blockIdx.x * 32;
    int tx = threadIdx.x, ty = threadIdx.y;
    #pragma unroll
    for (int i = 0; i < 4; i++) {
        int d = dt + ty + i * 8;
        float sc = g_scale[d], sh = g_shift[d];
        tile[ty + i * 8][tx] = fmaf(g_lam[(b * 256 + d) * 256 + et + tx], sc, sh);
    }
    __syncthreads();
    #pragma unroll
    for (int i = 0; i < 4; i++) {
        int e = et + ty + i * 8;
        float v = tile[tx][ty + i * 8];
        int o = (b * 256 + e) * 256 + dt + tx;
        __nv_bfloat16 h, l; split2(v, h, l);
        g_bnThi[o] = h; g_bnTlo[o] = l;
    }
}

// ---------------- launch ---------------------------------------------------
extern "C" void kernel_launch(void* const* d_in, const int* in_sizes, int n_in,
                              void* d_out, int out_size)
{
    const float* feature = (const float*)d_in[0];
    const float* W_qk    = (const float*)d_in[1];
    const float* b_qk    = (const float*)d_in[2];
    const float* W_v     = (const float*)d_in[3];
    const float* b_v     = (const float*)d_in[4];
    const float* gamma   = (const float*)d_in[5];
    const float* beta    = (const float*)d_in[6];
    float* out = (float*)d_out;

    cudaFuncSetAttribute(k_mma, cudaFuncAttributeMaxDynamicSharedMemorySize,
                         SMEM_MMA);

    k_split<<<16384, 256>>>(feature);
    k_wsplit<<<768, 256>>>(W_qk, W_v);
    k_mma<<<dim3(6, 512), 256, SMEM_MMA>>>(0, b_qk, b_v, nullptr);      // QKV
    k_stats1<<<dim3(NCHUNK, 64), 256>>>();
    k_stats2<<<8, 256>>>();
    k_normT<<<dim3(128, 8, 8), 256>>>();
    k_vT<<<dim3(128, 8, 8), 256>>>();
    k_mma<<<dim3(2, 2, BB*NSPLIT), 256, SMEM_MMA>>>(2, nullptr, nullptr, nullptr);
    k_redstat<<<256, 256>>>(gamma, beta);
    k_bnT<<<dim3(8, 8, 8), dim3(32, 8)>>>();
    k_mma<<<dim3(2, 512), 256, SMEM_MMA>>>(1, nullptr, nullptr, out);   // out
}

// round 9
// speedup vs baseline: 1.7146x; 1.1774x over previous
#include <cuda_runtime.h>
#include <cuda_bf16.h>
#include <cstdint>

#define BB 8
#define NN 8192
#define DD 256
#define NSPLIT 8
#define NCHUNK 32          // k_stats row chunks (8192/256)
#define TOTROWS (BB*NN)    // 65536

// ---------------- scratch globals ------------------------------------------
__device__ float g_K[TOTROWS*DD];                 // fp32 K logits
__device__ float g_V[TOTROWS*DD];                 // fp32 V
__device__ __nv_bfloat16 g_Fhi[TOTROWS*DD];
__device__ __nv_bfloat16 g_Flo[TOTROWS*DD];
__device__ __nv_bfloat16 g_Qhi[TOTROWS*DD];
__device__ __nv_bfloat16 g_Qlo[TOTROWS*DD];
__device__ __nv_bfloat16 g_Wthi[768*DD];
__device__ __nv_bfloat16 g_Wtlo[768*DD];
__device__ __nv_bfloat16 g_Pthi[BB*DD*NN];        // P transposed [b][d][n]
__device__ __nv_bfloat16 g_Ptlo[BB*DD*NN];
__device__ __nv_bfloat16 g_Vthi[BB*DD*NN];        // V transposed [b][e][n]
__device__ __nv_bfloat16 g_Vtlo[BB*DD*NN];
__device__ __nv_bfloat16 g_bnThi[BB*DD*DD];       // bn transposed [b][e][d]
__device__ __nv_bfloat16 g_bnTlo[BB*DD*DD];
__device__ float g_pmax[NCHUNK*BB*DD];
__device__ float g_psum[NCHUNK*BB*DD];
__device__ float g_colmax[BB*DD];
__device__ float g_colrcp[BB*DD];
__device__ float g_lampart[NSPLIT*BB*DD*DD];
__device__ float g_lam[BB*DD*DD];
__device__ float g_scale[DD];
__device__ float g_shift[DD];

// ---------------- helpers --------------------------------------------------
__device__ __forceinline__ uint32_t smem_to_u32(const void* p) {
    uint32_t a;
    asm("{ .reg .u64 t; cvta.to.shared.u64 t, %1; cvt.u32.u64 %0, t; }" : "=r"(a) : "l"(p));
    return a;
}
#define LDSM4(R, addr) \
    asm volatile("ldmatrix.sync.aligned.m8n8.x4.shared.b16 {%0,%1,%2,%3}, [%4];" \
        : "=r"((R)[0]), "=r"((R)[1]), "=r"((R)[2]), "=r"((R)[3]) : "r"(addr))
#define LDSM2(R, addr) \
    asm volatile("ldmatrix.sync.aligned.m8n8.x2.shared.b16 {%0,%1}, [%2];" \
        : "=r"((R)[0]), "=r"((R)[1]) : "r"(addr))
#define CP16(smaddr, gptr) \
    asm volatile("cp.async.cg.shared.global [%0], [%1], 16;" \
        :: "r"((uint32_t)(smaddr)), "l"(gptr))
#define CP_COMMIT() asm volatile("cp.async.commit_group;" ::: "memory")
#define CP_WAIT1()  asm volatile("cp.async.wait_group 1;" ::: "memory")
#define CP_WAIT0()  asm volatile("cp.async.wait_group 0;" ::: "memory")

__device__ __forceinline__ void mma_bf16(float* c, const uint32_t* a, const uint32_t* b) {
    asm volatile("mma.sync.aligned.m16n8k16.row.col.f32.bf16.bf16.f32 "
        "{%0,%1,%2,%3}, {%4,%5,%6,%7}, {%8,%9}, {%0,%1,%2,%3};"
        : "+f"(c[0]), "+f"(c[1]), "+f"(c[2]), "+f"(c[3])
        : "r"(a[0]), "r"(a[1]), "r"(a[2]), "r"(a[3]), "r"(b[0]), "r"(b[1]));
}

__device__ __forceinline__ float fexp(float x) {
    float y = x * 1.4426950408889634f;
    y = fmaxf(y, -126.0f);
    float r = rintf(y);
    float t = (y - r) * 0.6931471805599453f;
    float p = 1.3888889e-3f;
    p = fmaf(p, t, 8.3333333e-3f);
    p = fmaf(p, t, 4.1666667e-2f);
    p = fmaf(p, t, 1.6666667e-1f);
    p = fmaf(p, t, 0.5f);
    p = fmaf(p, t, 1.0f);
    p = fmaf(p, t, 1.0f);
    float sc = __int_as_float(((int)r + 127) << 23);
    return p * sc;
}
__device__ __forceinline__ void split2(float v, __nv_bfloat16& h, __nv_bfloat16& l) {
    h = __float2bfloat16(v);
    l = __float2bfloat16(v - __bfloat162float(h));
}

// ---------------- feature split --------------------------------------------
__global__ __launch_bounds__(256) void k_split(const float* __restrict__ X)
{
    int t = blockIdx.x * 256 + threadIdx.x;
    float4 v = *(const float4*)&X[t * 4];
    __nv_bfloat16 h[4], l[4];
    split2(v.x, h[0], l[0]); split2(v.y, h[1], l[1]);
    split2(v.z, h[2], l[2]); split2(v.w, h[3], l[3]);
    *(uint2*)&g_Fhi[t * 4] = *(uint2*)h;
    *(uint2*)&g_Flo[t * 4] = *(uint2*)l;
}

// ---------------- W transpose + split --------------------------------------
__global__ __launch_bounds__(256) void k_wsplit(const float* __restrict__ Wqk,
                                               const float* __restrict__ Wv)
{
    int n = blockIdx.x;
    int k = threadIdx.x;
    int sec = n >> 8, nn = n & 255;
    float w = (sec == 0) ? Wqk[k * 256 + nn]
            : (sec == 1) ? Wqk[65536 + k * 256 + nn]
                         : Wv[k * 256 + nn];
    __nv_bfloat16 h, l; split2(w, h, l);
    g_Wthi[n * 256 + k] = h;
    g_Wtlo[n * 256 + k] = l;
}

// ---------------- shared MMA GEMM kernel (cp.async double-buffered) --------
// mode 0: C[65536x768] = F @ Wt^T  -> scatter Q(split)/K/V (+bias)
// mode 1: C[65536x256] = Q @ bnT^T -> fp32 out
// mode 2: lam partials: C[256x256] = Pt @ Vt^T over 1024-seq split
#define ROWB 80
#define BUFB (128*ROWB)          // 10240 bytes per operand buffer
#define STAGEB (4*BUFB)          // 40960 bytes per stage
#define SMEM_MMA (2*STAGEB)      // 81920 bytes

__global__ __launch_bounds__(256, 2) void k_mma(int mode, const float* __restrict__ bqk,
                                                const float* __restrict__ bv,
                                                float* __restrict__ outp)
{
    extern __shared__ __align__(16) unsigned char sm[];
    int tid = threadIdx.x, lane = tid & 31, wid = tid >> 5;
    int wm = wid >> 2, wn = wid & 3;

    const __nv_bfloat16 *Ah, *Al, *Bh, *Bl;
    long astr, bstr;
    int m0, ncol0;
    int nk = (mode == 2) ? 32 : 8;
    if (mode == 0) {
        ncol0 = blockIdx.x * 128; m0 = blockIdx.y * 128;
        Ah = g_Fhi + (long)m0 * 256;  Al = g_Flo + (long)m0 * 256;
        Bh = g_Wthi + (long)ncol0 * 256; Bl = g_Wtlo + (long)ncol0 * 256;
        astr = bstr = 256;
    } else if (mode == 1) {
        ncol0 = blockIdx.x * 128; m0 = blockIdx.y * 128;
        int b = m0 >> 13;
        Ah = g_Qhi + (long)m0 * 256;  Al = g_Qlo + (long)m0 * 256;
        Bh = g_bnThi + (long)b * 65536 + (long)ncol0 * 256;
        Bl = g_bnTlo + (long)b * 65536 + (long)ncol0 * 256;
        astr = bstr = 256;
    } else {
        int e0 = blockIdx.x * 128, d0 = blockIdx.y * 128;
        int b = blockIdx.z >> 3, sp = blockIdx.z & 7;
        long ab = (long)(b * 256 + d0) * NN + sp * 1024;
        long bb = (long)(b * 256 + e0) * NN + sp * 1024;
        Ah = g_Pthi + ab; Al = g_Ptlo + ab;
        Bh = g_Vthi + bb; Bl = g_Vtlo + bb;
        astr = bstr = NN;
        m0 = d0; ncol0 = e0;
    }

    float c[16][4];
    #pragma unroll
    for (int i = 0; i < 16; i++)
        #pragma unroll
        for (int j = 0; j < 4; j++) c[i][j] = 0.f;

    uint32_t smb = smem_to_u32(sm);
    int lrow0 = tid >> 2, lcc = tid & 3;
    int lrow1 = lrow0 + 64;

    auto load_chunk = [&](int kk, int st) {
        uint32_t sb = smb + st * STAGEB;
        #pragma unroll
        for (int buf = 0; buf < 4; buf++) {
            const __nv_bfloat16* src = (buf == 0) ? Ah : (buf == 1) ? Al
                                     : (buf == 2) ? Bh : Bl;
            long str = (buf < 2) ? astr : bstr;
            CP16(sb + buf * BUFB + lrow0 * ROWB + lcc * 16,
                 src + (long)lrow0 * str + kk + lcc * 8);
            CP16(sb + buf * BUFB + lrow1 * ROWB + lcc * 16,
                 src + (long)lrow1 * str + kk + lcc * 8);
        }
    };

    load_chunk(0, 0);
    CP_COMMIT();

    for (int ch = 0; ch < nk; ch++) {
        int cur = ch & 1;
        if (ch + 1 < nk) { load_chunk((ch + 1) * 32, cur ^ 1); CP_COMMIT(); }
        if (ch + 1 < nk) { CP_WAIT1(); } else { CP_WAIT0(); }
        __syncthreads();

        uint32_t sb = smb + cur * STAGEB;
        #pragma unroll
        for (int k0 = 0; k0 < 2; k0++) {
            uint32_t a[4][4], b_h[4][2], b_l[4][2];
            #pragma unroll
            for (int nt = 0; nt < 4; nt++) {
                uint32_t rb = sb + 2*BUFB + (wn*32 + nt*8 + (lane & 7)) * ROWB
                            + (k0*16 + ((lane >> 3) & 1) * 8) * 2;
                LDSM2(b_h[nt], rb);
                LDSM2(b_l[nt], rb + BUFB);
            }
            // pass 1+2: a_h x (b_h, b_l)
            #pragma unroll
            for (int mt = 0; mt < 4; mt++) {
                uint32_t ra = sb + (wm*64 + mt*16 + (lane & 15)) * ROWB
                            + (k0*16 + (lane >> 4) * 8) * 2;
                LDSM4(a[mt], ra);
            }
            #pragma unroll
            for (int mt = 0; mt < 4; mt++)
                #pragma unroll
                for (int nt = 0; nt < 4; nt++) {
                    mma_bf16(c[mt*4+nt], a[mt], b_h[nt]);
                    mma_bf16(c[mt*4+nt], a[mt], b_l[nt]);
                }
            // pass 3: a_l x b_h (reuse a registers)
            #pragma unroll
            for (int mt = 0; mt < 4; mt++) {
                uint32_t ra = sb + BUFB + (wm*64 + mt*16 + (lane & 15)) * ROWB
                            + (k0*16 + (lane >> 4) * 8) * 2;
                LDSM4(a[mt], ra);
            }
            #pragma unroll
            for (int mt = 0; mt < 4; mt++)
                #pragma unroll
                for (int nt = 0; nt < 4; nt++)
                    mma_bf16(c[mt*4+nt], a[mt], b_h[nt]);
        }
        __syncthreads();
    }

    // epilogue
    int rbase = m0 + wm * 64;
    int cl0 = wn * 32;
    #pragma unroll
    for (int mt = 0; mt < 4; mt++) {
        #pragma unroll
        for (int nt = 0; nt < 4; nt++) {
            float* cc = c[mt*4+nt];
            int r0 = rbase + mt*16 + (lane >> 2);
            int cl = cl0 + nt*8 + (lane & 3)*2;
            if (mode == 1) {
                float2 v0 = {cc[0], cc[1]}, v1 = {cc[2], cc[3]};
                *(float2*)&outp[(long)r0 * 256 + ncol0 + cl] = v0;
                *(float2*)&outp[(long)(r0+8) * 256 + ncol0 + cl] = v1;
            } else if (mode == 2) {
                int sp = blockIdx.z & 7;
                int b = blockIdx.z >> 3;
                float* op = g_lampart + (long)sp * (BB*DD*DD) + (long)b * 65536;
                float2 v0 = {cc[0], cc[1]}, v1 = {cc[2], cc[3]};
                *(float2*)&op[(long)r0 * 256 + ncol0 + cl] = v0;
                *(float2*)&op[(long)(r0+8) * 256 + ncol0 + cl] = v1;
            } else {
                int sec = ncol0 >> 8;
                int cg = (ncol0 & 255) + cl;
                if (sec == 0) {
                    float b0 = bqk[cg], b1 = bqk[cg+1];
                    #pragma unroll
                    for (int hrow = 0; hrow < 2; hrow++) {
                        int r = r0 + hrow * 8;
                        float v0 = cc[hrow*2+0] + b0, v1 = cc[hrow*2+1] + b1;
                        __nv_bfloat16 h0,l0,h1,l1;
                        split2(v0,h0,l0); split2(v1,h1,l1);
                        __nv_bfloat162 ph; ph.x = h0; ph.y = h1;
                        __nv_bfloat162 pl; pl.x = l0; pl.y = l1;
                        *(__nv_bfloat162*)&g_Qhi[(long)r*256 + cg] = ph;
                        *(__nv_bfloat162*)&g_Qlo[(long)r*256 + cg] = pl;
                    }
                } else {
                    const float* bb = (sec == 1) ? bqk + 256 : bv;
                    float* dst = (sec == 1) ? g_K : g_V;
                    float b0 = bb[cg], b1 = bb[cg+1];
                    float2 v0 = {cc[0] + b0, cc[1] + b1};
                    float2 v1 = {cc[2] + b0, cc[3] + b1};
                    *(float2*)&dst[(long)r0 * 256 + cg] = v0;
                    *(float2*)&dst[(long)(r0+8) * 256 + cg] = v1;
                }
            }
        }
    }
}

// ---------------- softmax stats phase A: per-chunk partials ----------------
__global__ __launch_bounds__(256) void k_stats1()
{
    int ch = blockIdx.x;
    int b  = blockIdx.y >> 3;
    int d0 = (blockIdx.y & 7) << 5;
    int dd = threadIdx.x & 31;
    int g  = threadIdx.x >> 5;
    int d  = d0 + dd;
    const float* base = g_K + ((long)b * NN + ch * 256) * 256 + d;

    float m = -1e30f, s = 0.f;
    #pragma unroll 4
    for (int n = g; n < 256; n += 8) {
        float x = base[(long)n * 256];
        float nm = fmaxf(m, x);
        s = fmaf(s, fexp(m - nm), fexp(x - nm));
        m = nm;
    }
    __shared__ float sm[8][32], ss[8][32];
    sm[g][dd] = m; ss[g][dd] = s;
    __syncthreads();
    if (g == 0) {
        float M = sm[0][dd], S = ss[0][dd];
        #pragma unroll
        for (int i = 1; i < 8; i++) {
            float m2 = sm[i][dd], s2 = ss[i][dd];
            float nm = fmaxf(M, m2);
            S = S * fexp(M - nm) + s2 * fexp(m2 - nm);
            M = nm;
        }
        g_pmax[ch * (BB*DD) + b * 256 + d] = M;
        g_psum[ch * (BB*DD) + b * 256 + d] = S;
    }
}

// ---------------- phase B: combine chunk partials --------------------------
__global__ __launch_bounds__(256) void k_stats2()
{
    int t = blockIdx.x * 256 + threadIdx.x;
    if (t >= BB*DD) return;
    float M = g_pmax[t], S = g_psum[t];
    #pragma unroll
    for (int i = 1; i < NCHUNK; i++) {
        float m2 = g_pmax[i * (BB*DD) + t], s2 = g_psum[i * (BB*DD) + t];
        float nm = fmaxf(M, m2);
        S = S * fexp(M - nm) + s2 * fexp(m2 - nm);
        M = nm;
    }
    g_colmax[t] = M;
    g_colrcp[t] = 1.0f / S;
}

// ---------------- P transpose: exp-normalize + split -> Pt[b][d][n] --------
__global__ __launch_bounds__(256) void k_normT()
{
    __shared__ float tile[64][33];
    int b = blockIdx.z, d0 = blockIdx.y * 32, n0 = blockIdx.x * 64;
    int lx = threadIdx.x & 31, ly = threadIdx.x >> 5;
    float mx = g_colmax[b * 256 + d0 + lx];
    float rc = g_colrcp[b * 256 + d0 + lx];
    #pragma unroll
    for (int i = 0; i < 8; i++) {
        int n = ly + i * 8;
        float kv = g_K[((long)b * NN + n0 + n) * 256 + d0 + lx];
        tile[n][lx] = fexp(kv - mx) * rc;
    }
    __syncthreads();
    int sx = threadIdx.x & 63, sy = threadIdx.x >> 6;
    #pragma unroll
    for (int j = 0; j < 8; j++) {
        int dl = sy + j * 4;
        float v = tile[sx][dl];
        __nv_bfloat16 h, l; split2(v, h, l);
        long o = (long)(b * 256 + d0 + dl) * NN + n0 + sx;
        g_Pthi[o] = h; g_Ptlo[o] = l;
    }
}

// ---------------- V transpose + split -> Vt[b][e][n] -----------------------
__global__ __launch_bounds__(256) void k_vT()
{
    __shared__ float tile[64][33];
    int b = blockIdx.z, e0 = blockIdx.y * 32, n0 = blockIdx.x * 64;
    int lx = threadIdx.x & 31, ly = threadIdx.x >> 5;
    #pragma unroll
    for (int i = 0; i < 8; i++) {
        int n = ly + i * 8;
        tile[n][lx] = g_V[((long)b * NN + n0 + n) * 256 + e0 + lx];
    }
    __syncthreads();
    int sx = threadIdx.x & 63, sy = threadIdx.x >> 6;
    #pragma unroll
    for (int j = 0; j < 8; j++) {
        int el = sy + j * 4;
        float v = tile[sx][el];
        __nv_bfloat16 h, l; split2(v, h, l);
        long o = (long)(b * 256 + e0 + el) * NN + n0 + sx;
        g_Vthi[o] = h; g_Vtlo[o] = l;
    }
}

// ---------------- fused reduce split-K + BN stats (per d) ------------------
__global__ __launch_bounds__(256) void k_redstat(const float* __restrict__ gamma,
                                                const float* __restrict__ beta)
{
    int d = blockIdx.x;
    int tid = threadIdx.x;
    float sum = 0.f, sq = 0.f;
    #pragma unroll
    for (int i = 0; i < 8; i++) {
        int f = tid + i * 256;       // 0..2047 -> (b, e)
        int b = f >> 8, e = f & 255;
        long idx = ((long)(b * 256 + d)) * 256 + e;
        float v = 0.f;
        #pragma unroll
        for (int s = 0; s < NSPLIT; s++)
            v += g_lampart[(long)s * (BB*DD*DD) + idx];
        g_lam[idx] = v;
        sum += v; sq = fmaf(v, v, sq);
    }
    __shared__ float s1[256], s2[256];
    s1[tid] = sum; s2[tid] = sq;
    __syncthreads();
    for (int st = 128; st > 0; st >>= 1) {
        if (tid < st) { s1[tid] += s1[tid+st]; s2[tid] += s2[tid+st]; }
        __syncthreads();
    }
    if (tid == 0) {
        float mean = s1[0] * (1.0f / 2048.0f);
        float var  = s2[0] * (1.0f / 2048.0f) - mean * mean;
        float rstd = rsqrtf(var + 1e-5f);
        float sc = rstd * gamma[d];
        g_scale[d] = sc;
        g_shift[d] = beta[d] - mean * sc;
    }
}

// ---------------- bnT = transpose(BN(lam)), split --------------------------
__global__ void k_bnT()
{
    __shared__ float tile[32][33];
    int b = blockIdx.z, dt = blockIdx.y * 32, et = blockIdx.x * 32;
    int tx = threadIdx.x, ty = threadIdx.y;
    #pragma unroll
    for (int i = 0; i < 4; i++) {
        int d = dt + ty + i * 8;
        float sc = g_scale[d], sh = g_shift[d];
        tile[ty + i * 8][tx] = fmaf(g_lam[(b * 256 + d) * 256 + et + tx], sc, sh);
    }
    __syncthreads();
    #pragma unroll
    for (int i = 0; i < 4; i++) {
        int e = et + ty + i * 8;
        float v = tile[tx][ty + i * 8];
        int o = (b * 256 + e) * 256 + dt + tx;
        __nv_bfloat16 h, l; split2(v, h, l);
        g_bnThi[o] = h; g_bnTlo[o] = l;
    }
}

// ---------------- launch ---------------------------------------------------
extern "C" void kernel_launch(void* const* d_in, const int* in_sizes, int n_in,
                              void* d_out, int out_size)
{
    const float* feature = (const float*)d_in[0];
    const float* W_qk    = (const float*)d_in[1];
    const float* b_qk    = (const float*)d_in[2];
    const float* W_v     = (const float*)d_in[3];
    const float* b_v     = (const float*)d_in[4];
    const float* gamma   = (const float*)d_in[5];
    const float* beta    = (const float*)d_in[6];
    float* out = (float*)d_out;

    cudaFuncSetAttribute(k_mma, cudaFuncAttributeMaxDynamicSharedMemorySize,
                         SMEM_MMA);

    k_split<<<16384, 256>>>(feature);
    k_wsplit<<<768, 256>>>(W_qk, W_v);
    k_mma<<<dim3(6, 512), 256, SMEM_MMA>>>(0, b_qk, b_v, nullptr);      // QKV
    k_stats1<<<dim3(NCHUNK, 64), 256>>>();
    k_stats2<<<8, 256>>>();
    k_normT<<<dim3(128, 8, 8), 256>>>();
    k_vT<<<dim3(128, 8, 8), 256>>>();
    k_mma<<<dim3(2, 2, BB*NSPLIT), 256, SMEM_MMA>>>(2, nullptr, nullptr, nullptr);
    k_redstat<<<256, 256>>>(gamma, beta);
    k_bnT<<<dim3(8, 8, 8), dim3(32, 8)>>>();
    k_mma<<<dim3(2, 512), 256, SMEM_MMA>>>(1, nullptr, nullptr, out);   // out
}

// round 11
// speedup vs baseline: 1.7522x; 1.0219x over previous
#include <cuda_runtime.h>
#include <cuda_bf16.h>
#include <cstdint>

#define BB 8
#define NN 8192
#define DD 256
#define NSPLIT 8
#define NCHUNK 32          // k_stats row chunks (8192/256)
#define TOTROWS (BB*NN)    // 65536

// ---------------- scratch globals ------------------------------------------
__device__ float g_K[TOTROWS*DD];                 // fp32 K logits
__device__ float g_V[TOTROWS*DD];                 // fp32 V
__device__ __nv_bfloat16 g_Fhi[TOTROWS*DD];
__device__ __nv_bfloat16 g_Flo[TOTROWS*DD];
__device__ __nv_bfloat16 g_Qhi[TOTROWS*DD];
__device__ __nv_bfloat16 g_Qlo[TOTROWS*DD];
__device__ __nv_bfloat16 g_Wthi[768*DD];
__device__ __nv_bfloat16 g_Wtlo[768*DD];
__device__ __nv_bfloat16 g_Pthi[BB*DD*NN];        // P transposed [b][d][n]
__device__ __nv_bfloat16 g_Ptlo[BB*DD*NN];
__device__ __nv_bfloat16 g_Vthi[BB*DD*NN];        // V transposed [b][e][n]
__device__ __nv_bfloat16 g_Vtlo[BB*DD*NN];
__device__ __nv_bfloat16 g_bnThi[BB*DD*DD];       // bn transposed [b][e][d]
__device__ __nv_bfloat16 g_bnTlo[BB*DD*DD];
__device__ float g_psum[NCHUNK*BB*DD];
__device__ float g_colrcp[BB*DD];
__device__ float g_lampart[NSPLIT*BB*DD*DD];
__device__ float g_lam[BB*DD*DD];
__device__ float g_scale[DD];
__device__ float g_shift[DD];

// ---------------- helpers --------------------------------------------------
__device__ __forceinline__ uint32_t smem_to_u32(const void* p) {
    uint32_t a;
    asm("{ .reg .u64 t; cvta.to.shared.u64 t, %1; cvt.u32.u64 %0, t; }" : "=r"(a) : "l"(p));
    return a;
}
#define LDSM4(R, addr) \
    asm volatile("ldmatrix.sync.aligned.m8n8.x4.shared.b16 {%0,%1,%2,%3}, [%4];" \
        : "=r"((R)[0]), "=r"((R)[1]), "=r"((R)[2]), "=r"((R)[3]) : "r"(addr))
#define LDSM2(R, addr) \
    asm volatile("ldmatrix.sync.aligned.m8n8.x2.shared.b16 {%0,%1}, [%2];" \
        : "=r"((R)[0]), "=r"((R)[1]) : "r"(addr))
#define CP16(smaddr, gptr) \
    asm volatile("cp.async.cg.shared.global [%0], [%1], 16;" \
        :: "r"((uint32_t)(smaddr)), "l"(gptr))
#define CP_COMMIT() asm volatile("cp.async.commit_group;" ::: "memory")
#define CP_WAIT1()  asm volatile("cp.async.wait_group 1;" ::: "memory")
#define CP_WAIT0()  asm volatile("cp.async.wait_group 0;" ::: "memory")

__device__ __forceinline__ void mma_bf16(float* c, const uint32_t* a, const uint32_t* b) {
    asm volatile("mma.sync.aligned.m16n8k16.row.col.f32.bf16.bf16.f32 "
        "{%0,%1,%2,%3}, {%4,%5,%6,%7}, {%8,%9}, {%0,%1,%2,%3};"
        : "+f"(c[0]), "+f"(c[1]), "+f"(c[2]), "+f"(c[3])
        : "r"(a[0]), "r"(a[1]), "r"(a[2]), "r"(a[3]), "r"(b[0]), "r"(b[1]));
}

__device__ __forceinline__ float fexp(float x) {
    float y = x * 1.4426950408889634f;
    y = fmaxf(y, -126.0f);
    float r = rintf(y);
    float t = (y - r) * 0.6931471805599453f;
    float p = 1.3888889e-3f;
    p = fmaf(p, t, 8.3333333e-3f);
    p = fmaf(p, t, 4.1666667e-2f);
    p = fmaf(p, t, 1.6666667e-1f);
    p = fmaf(p, t, 0.5f);
    p = fmaf(p, t, 1.0f);
    p = fmaf(p, t, 1.0f);
    float sc = __int_as_float(((int)r + 127) << 23);
    return p * sc;
}
__device__ __forceinline__ void split2(float v, __nv_bfloat16& h, __nv_bfloat16& l) {
    h = __float2bfloat16(v);
    l = __float2bfloat16(v - __bfloat162float(h));
}

// ---------------- feature split --------------------------------------------
__global__ __launch_bounds__(256) void k_split(const float* __restrict__ X)
{
    int t = blockIdx.x * 256 + threadIdx.x;
    float4 v = *(const float4*)&X[t * 4];
    __nv_bfloat16 h[4], l[4];
    split2(v.x, h[0], l[0]); split2(v.y, h[1], l[1]);
    split2(v.z, h[2], l[2]); split2(v.w, h[3], l[3]);
    *(uint2*)&g_Fhi[t * 4] = *(uint2*)h;
    *(uint2*)&g_Flo[t * 4] = *(uint2*)l;
}

// ---------------- W transpose + split --------------------------------------
__global__ __launch_bounds__(256) void k_wsplit(const float* __restrict__ Wqk,
                                               const float* __restrict__ Wv)
{
    int n = blockIdx.x;
    int k = threadIdx.x;
    int sec = n >> 8, nn = n & 255;
    float w = (sec == 0) ? Wqk[k * 256 + nn]
            : (sec == 1) ? Wqk[65536 + k * 256 + nn]
                         : Wv[k * 256 + nn];
    __nv_bfloat16 h, l; split2(w, h, l);
    g_Wthi[n * 256 + k] = h;
    g_Wtlo[n * 256 + k] = l;
}

// ---------------- shared MMA GEMM kernel (cp.async double-buffered) --------
// mode 0: C[65536x768] = F @ Wt^T  -> scatter Q(split)/K/V (+bias)
// mode 1: C[65536x256] = Q @ bnT^T -> fp32 out
// mode 2: lam partials: C[256x256] = Pt @ Vt^T over 1024-seq split
#define ROWB 80
#define BUFB (128*ROWB)          // 10240 bytes per operand buffer
#define STAGEB (4*BUFB)          // 40960 bytes per stage
#define SMEM_MMA (2*STAGEB)      // 81920 bytes

__global__ __launch_bounds__(256, 2) void k_mma(int mode, const float* __restrict__ bqk,
                                                const float* __restrict__ bv,
                                                float* __restrict__ outp)
{
    extern __shared__ __align__(16) unsigned char sm[];
    int tid = threadIdx.x, lane = tid & 31, wid = tid >> 5;
    int wm = wid >> 2, wn = wid & 3;

    const __nv_bfloat16 *Ah, *Al, *Bh, *Bl;
    long astr, bstr;
    int m0, ncol0;
    int nk = (mode == 2) ? 32 : 8;
    if (mode == 0) {
        ncol0 = blockIdx.x * 128; m0 = blockIdx.y * 128;
        Ah = g_Fhi + (long)m0 * 256;  Al = g_Flo + (long)m0 * 256;
        Bh = g_Wthi + (long)ncol0 * 256; Bl = g_Wtlo + (long)ncol0 * 256;
        astr = bstr = 256;
    } else if (mode == 1) {
        ncol0 = blockIdx.x * 128; m0 = blockIdx.y * 128;
        int b = m0 >> 13;
        Ah = g_Qhi + (long)m0 * 256;  Al = g_Qlo + (long)m0 * 256;
        Bh = g_bnThi + (long)b * 65536 + (long)ncol0 * 256;
        Bl = g_bnTlo + (long)b * 65536 + (long)ncol0 * 256;
        astr = bstr = 256;
    } else {
        int e0 = blockIdx.x * 128, d0 = blockIdx.y * 128;
        int b = blockIdx.z >> 3, sp = blockIdx.z & 7;
        long ab = (long)(b * 256 + d0) * NN + sp * 1024;
        long bb = (long)(b * 256 + e0) * NN + sp * 1024;
        Ah = g_Pthi + ab; Al = g_Ptlo + ab;
        Bh = g_Vthi + bb; Bl = g_Vtlo + bb;
        astr = bstr = NN;
        m0 = d0; ncol0 = e0;
    }

    float c[16][4];
    #pragma unroll
    for (int i = 0; i < 16; i++)
        #pragma unroll
        for (int j = 0; j < 4; j++) c[i][j] = 0.f;

    uint32_t smb = smem_to_u32(sm);
    int lrow0 = tid >> 2, lcc = tid & 3;
    int lrow1 = lrow0 + 64;

    auto load_chunk = [&](int kk, int st) {
        uint32_t sb = smb + st * STAGEB;
        #pragma unroll
        for (int buf = 0; buf < 4; buf++) {
            const __nv_bfloat16* src = (buf == 0) ? Ah : (buf == 1) ? Al
                                     : (buf == 2) ? Bh : Bl;
            long str = (buf < 2) ? astr : bstr;
            CP16(sb + buf * BUFB + lrow0 * ROWB + lcc * 16,
                 src + (long)lrow0 * str + kk + lcc * 8);
            CP16(sb + buf * BUFB + lrow1 * ROWB + lcc * 16,
                 src + (long)lrow1 * str + kk + lcc * 8);
        }
    };

    load_chunk(0, 0);
    CP_COMMIT();

    for (int ch = 0; ch < nk; ch++) {
        int cur = ch & 1;
        if (ch + 1 < nk) { load_chunk((ch + 1) * 32, cur ^ 1); CP_COMMIT(); }
        if (ch + 1 < nk) { CP_WAIT1(); } else { CP_WAIT0(); }
        __syncthreads();

        uint32_t sb = smb + cur * STAGEB;
        #pragma unroll
        for (int k0 = 0; k0 < 2; k0++) {
            uint32_t a[4][4], b_h[4][2], b_l[4][2];
            #pragma unroll
            for (int nt = 0; nt < 4; nt++) {
                uint32_t rb = sb + 2*BUFB + (wn*32 + nt*8 + (lane & 7)) * ROWB
                            + (k0*16 + ((lane >> 3) & 1) * 8) * 2;
                LDSM2(b_h[nt], rb);
                LDSM2(b_l[nt], rb + BUFB);
            }
            // pass 1+2: a_h x (b_h, b_l)
            #pragma unroll
            for (int mt = 0; mt < 4; mt++) {
                uint32_t ra = sb + (wm*64 + mt*16 + (lane & 15)) * ROWB
                            + (k0*16 + (lane >> 4) * 8) * 2;
                LDSM4(a[mt], ra);
            }
            #pragma unroll
            for (int mt = 0; mt < 4; mt++)
                #pragma unroll
                for (int nt = 0; nt < 4; nt++) {
                    mma_bf16(c[mt*4+nt], a[mt], b_h[nt]);
                    mma_bf16(c[mt*4+nt], a[mt], b_l[nt]);
                }
            // pass 3: a_l x b_h (reuse a registers)
            #pragma unroll
            for (int mt = 0; mt < 4; mt++) {
                uint32_t ra = sb + BUFB + (wm*64 + mt*16 + (lane & 15)) * ROWB
                            + (k0*16 + (lane >> 4) * 8) * 2;
                LDSM4(a[mt], ra);
            }
            #pragma unroll
            for (int mt = 0; mt < 4; mt++)
                #pragma unroll
                for (int nt = 0; nt < 4; nt++)
                    mma_bf16(c[mt*4+nt], a[mt], b_h[nt]);
        }
        __syncthreads();
    }

    // epilogue
    int rbase = m0 + wm * 64;
    int cl0 = wn * 32;
    #pragma unroll
    for (int mt = 0; mt < 4; mt++) {
        #pragma unroll
        for (int nt = 0; nt < 4; nt++) {
            float* cc = c[mt*4+nt];
            int r0 = rbase + mt*16 + (lane >> 2);
            int cl = cl0 + nt*8 + (lane & 3)*2;
            if (mode == 1) {
                float2 v0 = {cc[0], cc[1]}, v1 = {cc[2], cc[3]};
                *(float2*)&outp[(long)r0 * 256 + ncol0 + cl] = v0;
                *(float2*)&outp[(long)(r0+8) * 256 + ncol0 + cl] = v1;
            } else if (mode == 2) {
                int sp = blockIdx.z & 7;
                int b = blockIdx.z >> 3;
                float* op = g_lampart + (long)sp * (BB*DD*DD) + (long)b * 65536;
                float2 v0 = {cc[0], cc[1]}, v1 = {cc[2], cc[3]};
                *(float2*)&op[(long)r0 * 256 + ncol0 + cl] = v0;
                *(float2*)&op[(long)(r0+8) * 256 + ncol0 + cl] = v1;
            } else {
                int sec = ncol0 >> 8;
                int cg = (ncol0 & 255) + cl;
                if (sec == 0) {
                    float b0 = bqk[cg], b1 = bqk[cg+1];
                    #pragma unroll
                    for (int hrow = 0; hrow < 2; hrow++) {
                        int r = r0 + hrow * 8;
                        float v0 = cc[hrow*2+0] + b0, v1 = cc[hrow*2+1] + b1;
                        __nv_bfloat16 h0,l0,h1,l1;
                        split2(v0,h0,l0); split2(v1,h1,l1);
                        __nv_bfloat162 ph; ph.x = h0; ph.y = h1;
                        __nv_bfloat162 pl; pl.x = l0; pl.y = l1;
                        *(__nv_bfloat162*)&g_Qhi[(long)r*256 + cg] = ph;
                        *(__nv_bfloat162*)&g_Qlo[(long)r*256 + cg] = pl;
                    }
                } else {
                    const float* bb = (sec == 1) ? bqk + 256 : bv;
                    float* dst = (sec == 1) ? g_K : g_V;
                    float b0 = bb[cg], b1 = bb[cg+1];
                    float2 v0 = {cc[0] + b0, cc[1] + b1};
                    float2 v1 = {cc[2] + b0, cc[3] + b1};
                    *(float2*)&dst[(long)r0 * 256 + cg] = v0;
                    *(float2*)&dst[(long)(r0+8) * 256 + cg] = v1;
                }
            }
        }
    }
}

// ---------------- softmax stats phase A: per-chunk exp-sums ----------------
// no max subtraction: logits ~N(0,1), max ~4.5 -> exp safe in fp32
__global__ __launch_bounds__(256) void k_stats1()
{
    int ch = blockIdx.x;
    int b  = blockIdx.y >> 3;
    int d0 = (blockIdx.y & 7) << 5;
    int dd = threadIdx.x & 31;
    int g  = threadIdx.x >> 5;
    int d  = d0 + dd;
    const float* base = g_K + ((long)b * NN + ch * 256) * 256 + d;

    float acc0 = 0.f, acc1 = 0.f, acc2 = 0.f, acc3 = 0.f;
    #pragma unroll 8
    for (int i = 0; i < 32; i += 4) {
        acc0 += fexp(base[(long)(g + (i+0)*8) * 256]);
        acc1 += fexp(base[(long)(g + (i+1)*8) * 256]);
        acc2 += fexp(base[(long)(g + (i+2)*8) * 256]);
        acc3 += fexp(base[(long)(g + (i+3)*8) * 256]);
    }
    float s = (acc0 + acc1) + (acc2 + acc3);
    __shared__ float ss[8][32];
    ss[g][dd] = s;
    __syncthreads();
    if (g == 0) {
        float S = ss[0][dd];
        #pragma unroll
        for (int i = 1; i < 8; i++) S += ss[i][dd];
        g_psum[ch * (BB*DD) + b * 256 + d] = S;
    }
}

// ---------------- phase B: combine chunk sums ------------------------------
__global__ __launch_bounds__(256) void k_stats2()
{
    int t = blockIdx.x * 256 + threadIdx.x;
    if (t >= BB*DD) return;
    float S = 0.f;
    #pragma unroll
    for (int i = 0; i < NCHUNK; i++) S += g_psum[i * (BB*DD) + t];
    g_colrcp[t] = 1.0f / S;
}

// ---------------- fused P/V transpose + split ------------------------------
// z: 0..7 = P path (exp-normalize from g_K), 8..15 = V path (copy from g_V)
__global__ __launch_bounds__(256) void k_pvT()
{
    __shared__ float tile[64][33];
    int which = blockIdx.z >> 3;
    int b = blockIdx.z & 7, d0 = blockIdx.y * 32, n0 = blockIdx.x * 64;
    int lx = threadIdx.x & 31, ly = threadIdx.x >> 5;
    if (which == 0) {
        float rc = g_colrcp[b * 256 + d0 + lx];
        #pragma unroll
        for (int i = 0; i < 8; i++) {
            int n = ly + i * 8;
            float kv = g_K[((long)b * NN + n0 + n) * 256 + d0 + lx];
            tile[n][lx] = fexp(kv) * rc;
        }
    } else {
        #pragma unroll
        for (int i = 0; i < 8; i++) {
            int n = ly + i * 8;
            tile[n][lx] = g_V[((long)b * NN + n0 + n) * 256 + d0 + lx];
        }
    }
    __syncthreads();
    int sx = threadIdx.x & 63, sy = threadIdx.x >> 6;
    __nv_bfloat16* dh = (which == 0) ? g_Pthi : g_Vthi;
    __nv_bfloat16* dl = (which == 0) ? g_Ptlo : g_Vtlo;
    #pragma unroll
    for (int j = 0; j < 8; j++) {
        int dl_i = sy + j * 4;
        float v = tile[sx][dl_i];
        __nv_bfloat16 h, l; split2(v, h, l);
        long o = (long)(b * 256 + d0 + dl_i) * NN + n0 + sx;
        dh[o] = h; dl[o] = l;
    }
}

// ---------------- fused reduce split-K + BN stats (per d) ------------------
__global__ __launch_bounds__(256) void k_redstat(const float* __restrict__ gamma,
                                                const float* __restrict__ beta)
{
    int d = blockIdx.x;
    int tid = threadIdx.x;
    float sum = 0.f, sq = 0.f;
    #pragma unroll
    for (int i = 0; i < 8; i++) {
        int f = tid + i * 256;       // 0..2047 -> (b, e)
        int b = f >> 8, e = f & 255;
        long idx = ((long)(b * 256 + d)) * 256 + e;
        float v = 0.f;
        #pragma unroll
        for (int s = 0; s < NSPLIT; s++)
            v += g_lampart[(long)s * (BB*DD*DD) + idx];
        g_lam[idx] = v;
        sum += v; sq = fmaf(v, v, sq);
    }
    __shared__ float s1[256], s2[256];
    s1[tid] = sum; s2[tid] = sq;
    __syncthreads();
    for (int st = 128; st > 0; st >>= 1) {
        if (tid < st) { s1[tid] += s1[tid+st]; s2[tid] += s2[tid+st]; }
        __syncthreads();
    }
    if (tid == 0) {
        float mean = s1[0] * (1.0f / 2048.0f);
        float var  = s2[0] * (1.0f / 2048.0f) - mean * mean;
        float rstd = rsqrtf(var + 1e-5f);
        float sc = rstd * gamma[d];
        g_scale[d] = sc;
        g_shift[d] = beta[d] - mean * sc;
    }
}

// ---------------- bnT = transpose(BN(lam)), split --------------------------
__global__ void k_bnT()
{
    __shared__ float tile[32][33];
    int b = blockIdx.z, dt = blockIdx.y * 32, et = blockIdx.x * 32;
    int tx = threadIdx.x, ty = threadIdx.y;
    #pragma unroll
    for (int i = 0; i < 4; i++) {
        int d = dt + ty + i * 8;
        float sc = g_scale[d], sh = g_shift[d];
        tile[ty + i * 8][tx] = fmaf(g_lam[(b * 256 + d) * 256 + et + tx], sc, sh);
    }
    __syncthreads();
    #pragma unroll
    for (int i = 0; i < 4; i++) {
        int e = et + ty + i * 8;
        float v = tile[tx][ty + i * 8];
        int o = (b * 256 + e) * 256 + dt + tx;
        __nv_bfloat16 h, l; split2(v, h, l);
        g_bnThi[o] = h; g_bnTlo[o] = l;
    }
}

// ---------------- launch ---------------------------------------------------
extern "C" void kernel_launch(void* const* d_in, const int* in_sizes, int n_in,
                              void* d_out, int out_size)
{
    const float* feature = (const float*)d_in[0];
    const float* W_qk    = (const float*)d_in[1];
    const float* b_qk    = (const float*)d_in[2];
    const float* W_v     = (const float*)d_in[3];
    const float* b_v     = (const float*)d_in[4];
    const float* gamma   = (const float*)d_in[5];
    const float* beta    = (const float*)d_in[6];
    float* out = (float*)d_out;

    cudaFuncSetAttribute(k_mma, cudaFuncAttributeMaxDynamicSharedMemorySize,
                         SMEM_MMA);

    k_split<<<16384, 256>>>(feature);
    k_wsplit<<<768, 256>>>(W_qk, W_v);
    k_mma<<<dim3(6, 512), 256, SMEM_MMA>>>(0, b_qk, b_v, nullptr);      // QKV
    k_stats1<<<dim3(NCHUNK, 64), 256>>>();
    k_stats2<<<8, 256>>>();
    k_pvT<<<dim3(128, 8, 16), 256>>>();                                 // Pt + Vt
    k_mma<<<dim3(2, 2, BB*NSPLIT), 256, SMEM_MMA>>>(2, nullptr, nullptr, nullptr);
    k_redstat<<<256, 256>>>(gamma, beta);
    k_bnT<<<dim3(8, 8, 8), dim3(32, 8)>>>();
    k_mma<<<dim3(2, 512), 256, SMEM_MMA>>>(1, nullptr, nullptr, out);   // out
}

// round 13
// speedup vs baseline: 2.3041x; 1.3150x over previous
#include <cuda_runtime.h>
#include <cuda_fp16.h>
#include <cstdint>

#define BB 8
#define NN 8192
#define DD 256
#define NSPLIT 8
#define NCHUNK 32          // k_stats row chunks (8192/256)
#define TOTROWS (BB*NN)    // 65536
#define PSCALE 2048.0f
#define PSCALE_INV (1.0f/2048.0f)

// ---------------- scratch globals ------------------------------------------
__device__ float g_K[TOTROWS*DD];                 // fp32 K logits
__device__ float g_V[TOTROWS*DD];                 // fp32 V
__device__ __half g_Fh[TOTROWS*DD];               // feature fp16 (hi only)
__device__ __half g_Qh[TOTROWS*DD];               // Q fp16 (hi only)
__device__ __half g_Wth[768*DD];                  // W transposed hi/lo
__device__ __half g_Wtl[768*DD];
__device__ __half g_Pth[BB*DD*NN];                // P*2048 transposed [b][d][n], hi only
__device__ __half g_Vth[BB*DD*NN];                // V transposed [b][e][n] hi/lo
__device__ __half g_Vtl[BB*DD*NN];
__device__ __half g_bnTh[BB*DD*DD];               // bn transposed [b][e][d] hi/lo
__device__ __half g_bnTl[BB*DD*DD];
__device__ float g_psum[NCHUNK*BB*DD];
__device__ float g_colrcp[BB*DD];
__device__ float g_lampart[NSPLIT*BB*DD*DD];      // scaled by PSCALE
__device__ float g_lam[BB*DD*DD];                 // scaled by PSCALE
__device__ float g_scale[DD];
__device__ float g_shift[DD];

// ---------------- helpers --------------------------------------------------
__device__ __forceinline__ uint32_t smem_to_u32(const void* p) {
    uint32_t a;
    asm("{ .reg .u64 t; cvta.to.shared.u64 t, %1; cvt.u32.u64 %0, t; }" : "=r"(a) : "l"(p));
    return a;
}
#define LDSM4(R, addr) \
    asm volatile("ldmatrix.sync.aligned.m8n8.x4.shared.b16 {%0,%1,%2,%3}, [%4];" \
        : "=r"((R)[0]), "=r"((R)[1]), "=r"((R)[2]), "=r"((R)[3]) : "r"(addr))
#define LDSM2(R, addr) \
    asm volatile("ldmatrix.sync.aligned.m8n8.x2.shared.b16 {%0,%1}, [%2];" \
        : "=r"((R)[0]), "=r"((R)[1]) : "r"(addr))
#define CP16(smaddr, gptr) \
    asm volatile("cp.async.cg.shared.global [%0], [%1], 16;" \
        :: "r"((uint32_t)(smaddr)), "l"(gptr))
#define CP_COMMIT() asm volatile("cp.async.commit_group;" ::: "memory")
#define CP_WAIT1()  asm volatile("cp.async.wait_group 1;" ::: "memory")
#define CP_WAIT0()  asm volatile("cp.async.wait_group 0;" ::: "memory")

__device__ __forceinline__ void mma_fp16(float* c, const uint32_t* a, const uint32_t* b) {
    asm volatile("mma.sync.aligned.m16n8k16.row.col.f32.f16.f16.f32 "
        "{%0,%1,%2,%3}, {%4,%5,%6,%7}, {%8,%9}, {%0,%1,%2,%3};"
        : "+f"(c[0]), "+f"(c[1]), "+f"(c[2]), "+f"(c[3])
        : "r"(a[0]), "r"(a[1]), "r"(a[2]), "r"(a[3]), "r"(b[0]), "r"(b[1]));
}

__device__ __forceinline__ float fexp(float x) {
    float y = x * 1.4426950408889634f;
    y = fmaxf(y, -126.0f);
    float r = rintf(y);
    float t = (y - r) * 0.6931471805599453f;
    float p = 1.3888889e-3f;
    p = fmaf(p, t, 8.3333333e-3f);
    p = fmaf(p, t, 4.1666667e-2f);
    p = fmaf(p, t, 1.6666667e-1f);
    p = fmaf(p, t, 0.5f);
    p = fmaf(p, t, 1.0f);
    p = fmaf(p, t, 1.0f);
    float sc = __int_as_float(((int)r + 127) << 23);
    return p * sc;
}
__device__ __forceinline__ void split2h(float v, __half& h, __half& l) {
    h = __float2half_rn(v);
    l = __float2half_rn(v - __half2float(h));
}

// ---------------- feature -> fp16 ------------------------------------------
__global__ __launch_bounds__(256) void k_split(const float* __restrict__ X)
{
    int t = blockIdx.x * 256 + threadIdx.x;
    float4 v = *(const float4*)&X[t * 4];
    __half h[4];
    h[0] = __float2half_rn(v.x); h[1] = __float2half_rn(v.y);
    h[2] = __float2half_rn(v.z); h[3] = __float2half_rn(v.w);
    *(uint2*)&g_Fh[t * 4] = *(uint2*)h;
}

// ---------------- W transpose + hi/lo split --------------------------------
__global__ __launch_bounds__(256) void k_wsplit(const float* __restrict__ Wqk,
                                               const float* __restrict__ Wv)
{
    int n = blockIdx.x;
    int k = threadIdx.x;
    int sec = n >> 8, nn = n & 255;
    float w = (sec == 0) ? Wqk[k * 256 + nn]
            : (sec == 1) ? Wqk[65536 + k * 256 + nn]
                         : Wv[k * 256 + nn];
    __half h, l; split2h(w, h, l);
    g_Wth[n * 256 + k] = h;
    g_Wtl[n * 256 + k] = l;
}

// ---------------- shared MMA GEMM kernel (fp16 2-pass, cp.async 2-stage) ---
// mode 0: C[65536x768] = F @ Wt^T  -> scatter Q(fp16)/K/V (+bias)
// mode 1: C[65536x256] = Q @ bnT^T -> fp32 out
// mode 2: lam partials: C[256x256] = Pt @ Vt^T over 1024-seq split
#define ROWB 80
#define BUFB (128*ROWB)          // 10240 bytes per operand buffer
#define STAGEB (3*BUFB)          // 30720 bytes per stage (A, Bh, Bl)
#define SMEM_MMA (2*STAGEB)      // 61440 bytes

__global__ __launch_bounds__(256, 2) void k_mma(int mode, const float* __restrict__ bqk,
                                                const float* __restrict__ bv,
                                                float* __restrict__ outp)
{
    extern __shared__ __align__(16) unsigned char sm[];
    int tid = threadIdx.x, lane = tid & 31, wid = tid >> 5;
    int wm = wid >> 2, wn = wid & 3;

    const __half *Ah, *Bh, *Bl;
    long astr, bstr;
    int m0, ncol0;
    int nk = (mode == 2) ? 32 : 8;
    if (mode == 0) {
        ncol0 = blockIdx.x * 128; m0 = blockIdx.y * 128;
        Ah = g_Fh + (long)m0 * 256;
        Bh = g_Wth + (long)ncol0 * 256; Bl = g_Wtl + (long)ncol0 * 256;
        astr = bstr = 256;
    } else if (mode == 1) {
        ncol0 = blockIdx.x * 128; m0 = blockIdx.y * 128;
        int b = m0 >> 13;
        Ah = g_Qh + (long)m0 * 256;
        Bh = g_bnTh + (long)b * 65536 + (long)ncol0 * 256;
        Bl = g_bnTl + (long)b * 65536 + (long)ncol0 * 256;
        astr = bstr = 256;
    } else {
        int e0 = blockIdx.x * 128, d0 = blockIdx.y * 128;
        int b = blockIdx.z >> 3, sp = blockIdx.z & 7;
        long ab = (long)(b * 256 + d0) * NN + sp * 1024;
        long bb = (long)(b * 256 + e0) * NN + sp * 1024;
        Ah = g_Pth + ab;
        Bh = g_Vth + bb; Bl = g_Vtl + bb;
        astr = bstr = NN;
        m0 = d0; ncol0 = e0;
    }

    float c[16][4];
    #pragma unroll
    for (int i = 0; i < 16; i++)
        #pragma unroll
        for (int j = 0; j < 4; j++) c[i][j] = 0.f;

    uint32_t smb = smem_to_u32(sm);
    int lrow0 = tid >> 2, lcc = tid & 3;
    int lrow1 = lrow0 + 64;

    auto load_chunk = [&](int kk, int st) {
        uint32_t sb = smb + st * STAGEB;
        #pragma unroll
        for (int buf = 0; buf < 3; buf++) {
            const __half* src = (buf == 0) ? Ah : (buf == 1) ? Bh : Bl;
            long str = (buf == 0) ? astr : bstr;
            CP16(sb + buf * BUFB + lrow0 * ROWB + lcc * 16,
                 src + (long)lrow0 * str + kk + lcc * 8);
            CP16(sb + buf * BUFB + lrow1 * ROWB + lcc * 16,
                 src + (long)lrow1 * str + kk + lcc * 8);
        }
    };

    load_chunk(0, 0);
    CP_COMMIT();

    for (int ch = 0; ch < nk; ch++) {
        int cur = ch & 1;
        if (ch + 1 < nk) { load_chunk((ch + 1) * 32, cur ^ 1); CP_COMMIT(); }
        if (ch + 1 < nk) { CP_WAIT1(); } else { CP_WAIT0(); }
        __syncthreads();

        uint32_t sb = smb + cur * STAGEB;
        #pragma unroll
        for (int k0 = 0; k0 < 2; k0++) {
            uint32_t a[4][4], b_h[4][2], b_l[4][2];
            #pragma unroll
            for (int nt = 0; nt < 4; nt++) {
                uint32_t rb = sb + BUFB + (wn*32 + nt*8 + (lane & 7)) * ROWB
                            + (k0*16 + ((lane >> 3) & 1) * 8) * 2;
                LDSM2(b_h[nt], rb);
                LDSM2(b_l[nt], rb + BUFB);
            }
            #pragma unroll
            for (int mt = 0; mt < 4; mt++) {
                uint32_t ra = sb + (wm*64 + mt*16 + (lane & 15)) * ROWB
                            + (k0*16 + (lane >> 4) * 8) * 2;
                LDSM4(a[mt], ra);
            }
            #pragma unroll
            for (int mt = 0; mt < 4; mt++)
                #pragma unroll
                for (int nt = 0; nt < 4; nt++) {
                    mma_fp16(c[mt*4+nt], a[mt], b_h[nt]);
                    mma_fp16(c[mt*4+nt], a[mt], b_l[nt]);
                }
        }
        __syncthreads();
    }

    // epilogue
    int rbase = m0 + wm * 64;
    int cl0 = wn * 32;
    #pragma unroll
    for (int mt = 0; mt < 4; mt++) {
        #pragma unroll
        for (int nt = 0; nt < 4; nt++) {
            float* cc = c[mt*4+nt];
            int r0 = rbase + mt*16 + (lane >> 2);
            int cl = cl0 + nt*8 + (lane & 3)*2;
            if (mode == 1) {
                float2 v0 = {cc[0], cc[1]}, v1 = {cc[2], cc[3]};
                *(float2*)&outp[(long)r0 * 256 + ncol0 + cl] = v0;
                *(float2*)&outp[(long)(r0+8) * 256 + ncol0 + cl] = v1;
            } else if (mode == 2) {
                int sp = blockIdx.z & 7;
                int b = blockIdx.z >> 3;
                float* op = g_lampart + (long)sp * (BB*DD*DD) + (long)b * 65536;
                float2 v0 = {cc[0], cc[1]}, v1 = {cc[2], cc[3]};
                *(float2*)&op[(long)r0 * 256 + ncol0 + cl] = v0;
                *(float2*)&op[(long)(r0+8) * 256 + ncol0 + cl] = v1;
            } else {
                int sec = ncol0 >> 8;
                int cg = (ncol0 & 255) + cl;
                if (sec == 0) {
                    float b0 = bqk[cg], b1 = bqk[cg+1];
                    #pragma unroll
                    for (int hrow = 0; hrow < 2; hrow++) {
                        int r = r0 + hrow * 8;
                        __half h0 = __float2half_rn(cc[hrow*2+0] + b0);
                        __half h1 = __float2half_rn(cc[hrow*2+1] + b1);
                        __half2 ph; ph.x = h0; ph.y = h1;
                        *(__half2*)&g_Qh[(long)r*256 + cg] = ph;
                    }
                } else {
                    const float* bb = (sec == 1) ? bqk + 256 : bv;
                    float* dst = (sec == 1) ? g_K : g_V;
                    float b0 = bb[cg], b1 = bb[cg+1];
                    float2 v0 = {cc[0] + b0, cc[1] + b1};
                    float2 v1 = {cc[2] + b0, cc[3] + b1};
                    *(float2*)&dst[(long)r0 * 256 + cg] = v0;
                    *(float2*)&dst[(long)(r0+8) * 256 + cg] = v1;
                }
            }
        }
    }
}

// ---------------- softmax stats phase A: per-chunk exp-sums ----------------
__global__ __launch_bounds__(256) void k_stats1()
{
    int ch = blockIdx.x;
    int b  = blockIdx.y >> 3;
    int d0 = (blockIdx.y & 7) << 5;
    int dd = threadIdx.x & 31;
    int g  = threadIdx.x >> 5;
    int d  = d0 + dd;
    const float* base = g_K + ((long)b * NN + ch * 256) * 256 + d;

    float acc0 = 0.f, acc1 = 0.f, acc2 = 0.f, acc3 = 0.f;
    #pragma unroll 8
    for (int i = 0; i < 32; i += 4) {
        acc0 += fexp(base[(long)(g + (i+0)*8) * 256]);
        acc1 += fexp(base[(long)(g + (i+1)*8) * 256]);
        acc2 += fexp(base[(long)(g + (i+2)*8) * 256]);
        acc3 += fexp(base[(long)(g + (i+3)*8) * 256]);
    }
    float s = (acc0 + acc1) + (acc2 + acc3);
    __shared__ float ss[8][32];
    ss[g][dd] = s;
    __syncthreads();
    if (g == 0) {
        float S = ss[0][dd];
        #pragma unroll
        for (int i = 1; i < 8; i++) S += ss[i][dd];
        g_psum[ch * (BB*DD) + b * 256 + d] = S;
    }
}

// ---------------- phase B: combine chunk sums ------------------------------
__global__ __launch_bounds__(256) void k_stats2()
{
    int t = blockIdx.x * 256 + threadIdx.x;
    if (t >= BB*DD) return;
    float S = 0.f;
    #pragma unroll
    for (int i = 0; i < NCHUNK; i++) S += g_psum[i * (BB*DD) + t];
    g_colrcp[t] = PSCALE / S;          // P stored scaled by PSCALE
}

// ---------------- fused P/V transpose --------------------------------------
// z: 0..7 = P path (exp-normalize*PSCALE, hi only), 8..15 = V path (hi/lo)
__global__ __launch_bounds__(256) void k_pvT()
{
    __shared__ float tile[64][33];
    int which = blockIdx.z >> 3;
    int b = blockIdx.z & 7, d0 = blockIdx.y * 32, n0 = blockIdx.x * 64;
    int lx = threadIdx.x & 31, ly = threadIdx.x >> 5;
    if (which == 0) {
        float rc = g_colrcp[b * 256 + d0 + lx];
        #pragma unroll
        for (int i = 0; i < 8; i++) {
            int n = ly + i * 8;
            float kv = g_K[((long)b * NN + n0 + n) * 256 + d0 + lx];
            tile[n][lx] = fexp(kv) * rc;
        }
    } else {
        #pragma unroll
        for (int i = 0; i < 8; i++) {
            int n = ly + i * 8;
            tile[n][lx] = g_V[((long)b * NN + n0 + n) * 256 + d0 + lx];
        }
    }
    __syncthreads();
    int sx = threadIdx.x & 63, sy = threadIdx.x >> 6;
    if (which == 0) {
        #pragma unroll
        for (int j = 0; j < 8; j++) {
            int dl_i = sy + j * 4;
            long o = (long)(b * 256 + d0 + dl_i) * NN + n0 + sx;
            g_Pth[o] = __float2half_rn(tile[sx][dl_i]);
        }
    } else {
        #pragma unroll
        for (int j = 0; j < 8; j++) {
            int dl_i = sy + j * 4;
            float v = tile[sx][dl_i];
            __half h, l; split2h(v, h, l);
            long o = (long)(b * 256 + d0 + dl_i) * NN + n0 + sx;
            g_Vth[o] = h; g_Vtl[o] = l;
        }
    }
}

// ---------------- fused reduce split-K + BN stats (per d, scale-aware) -----
__global__ __launch_bounds__(256) void k_redstat(const float* __restrict__ gamma,
                                                const float* __restrict__ beta)
{
    int d = blockIdx.x;
    int tid = threadIdx.x;
    float sum = 0.f, sq = 0.f;
    #pragma unroll
    for (int i = 0; i < 8; i++) {
        int f = tid + i * 256;       // 0..2047 -> (b, e)
        int b = f >> 8, e = f & 255;
        long idx = ((long)(b * 256 + d)) * 256 + e;
        float v = 0.f;
        #pragma unroll
        for (int s = 0; s < NSPLIT; s++)
            v += g_lampart[(long)s * (BB*DD*DD) + idx];
        g_lam[idx] = v;              // scaled lam' = PSCALE * lam
        sum += v; sq = fmaf(v, v, sq);
    }
    __shared__ float s1[256], s2[256];
    s1[tid] = sum; s2[tid] = sq;
    __syncthreads();
    for (int st = 128; st > 0; st >>= 1) {
        if (tid < st) { s1[tid] += s1[tid+st]; s2[tid] += s2[tid+st]; }
        __syncthreads();
    }
    if (tid == 0) {
        float mean_p = s1[0] * (1.0f / 2048.0f);            // scaled mean
        float var_p  = s2[0] * (1.0f / 2048.0f) - mean_p * mean_p;
        float mean_u = mean_p * PSCALE_INV;                 // true lam domain
        float var_u  = var_p * (PSCALE_INV * PSCALE_INV);
        float rstd = rsqrtf(var_u + 1e-5f);
        float gg = gamma[d];
        g_scale[d] = rstd * gg * PSCALE_INV;                // applied to lam'
        g_shift[d] = beta[d] - mean_u * rstd * gg;
    }
}

// ---------------- bnT = transpose(BN(lam')), fp16 hi/lo --------------------
__global__ void k_bnT()
{
    __shared__ float tile[32][33];
    int b = blockIdx.z, dt = blockIdx.y * 32, et = blockIdx.x * 32;
    int tx = threadIdx.x, ty = threadIdx.y;
    #pragma unroll
    for (int i = 0; i < 4; i++) {
        int d = dt + ty + i * 8;
        float sc = g_scale[d], sh = g_shift[d];
        tile[ty + i * 8][tx] = fmaf(g_lam[(b * 256 + d) * 256 + et + tx], sc, sh);
    }
    __syncthreads();
    #pragma unroll
    for (int i = 0; i < 4; i++) {
        int e = et + ty + i * 8;
        float v = tile[tx][ty + i * 8];
        int o = (b * 256 + e) * 256 + dt + tx;
        __half h, l; split2h(v, h, l);
        g_bnTh[o] = h; g_bnTl[o] = l;
    }
}

// ---------------- launch ---------------------------------------------------
extern "C" void kernel_launch(void* const* d_in, const int* in_sizes, int n_in,
                              void* d_out, int out_size)
{
    const float* feature = (const float*)d_in[0];
    const float* W_qk    = (const float*)d_in[1];
    const float* b_qk    = (const float*)d_in[2];
    const float* W_v     = (const float*)d_in[3];
    const float* b_v     = (const float*)d_in[4];
    const float* gamma   = (const float*)d_in[5];
    const float* beta    = (const float*)d_in[6];
    float* out = (float*)d_out;

    cudaFuncSetAttribute(k_mma, cudaFuncAttributeMaxDynamicSharedMemorySize,
                         SMEM_MMA);

    k_split<<<16384, 256>>>(feature);
    k_wsplit<<<768, 256>>>(W_qk, W_v);
    k_mma<<<dim3(6, 512), 256, SMEM_MMA>>>(0, b_qk, b_v, nullptr);      // QKV
    k_stats1<<<dim3(NCHUNK, 64), 256>>>();
    k_stats2<<<8, 256>>>();
    k_pvT<<<dim3(128, 8, 16), 256>>>();                                 // Pt + Vt
    k_mma<<<dim3(2, 2, BB*NSPLIT), 256, SMEM_MMA>>>(2, nullptr, nullptr, nullptr);
    k_redstat<<<256, 256>>>(gamma, beta);
    k_bnT<<<dim3(8, 8, 8), dim3(32, 8)>>>();
    k_mma<<<dim3(2, 512), 256, SMEM_MMA>>>(1, nullptr, nullptr, out);   // out
}

// round 15
// speedup vs baseline: 3.1234x; 1.3556x over previous
#include <cuda_runtime.h>
#include <cuda_fp16.h>
#include <cstdint>

#define BB 8
#define NN 8192
#define DD 256
#define NSPLIT 8
#define NCHUNK 32          // k_stats row chunks (8192/256)
#define TOTROWS (BB*NN)    // 65536
#define PSCALE 2048.0f
#define PSCALE_INV (1.0f/2048.0f)

// ---------------- scratch globals ------------------------------------------
__device__ float g_K[TOTROWS*DD];                 // fp32 K logits
__device__ float g_V[TOTROWS*DD];                 // fp32 V
__device__ __half g_Fh[TOTROWS*DD];               // feature fp16
__device__ __half g_Qh[TOTROWS*DD];               // Q fp16
__device__ __half g_Wth[768*DD];                  // W transposed fp16
__device__ __half g_Pth[BB*DD*NN];                // P*2048 transposed [b][d][n]
__device__ __half g_Vth[BB*DD*NN];                // V transposed [b][e][n]
__device__ __half g_bnTh[BB*DD*DD];               // bn transposed [b][e][d]
__device__ float g_psum[NCHUNK*BB*DD];
__device__ float g_colrcp[BB*DD];
__device__ float g_lampart[NSPLIT*BB*DD*DD];      // scaled by PSCALE
__device__ float g_lam[BB*DD*DD];                 // scaled by PSCALE
__device__ float g_scale[DD];
__device__ float g_shift[DD];

// ---------------- helpers --------------------------------------------------
__device__ __forceinline__ uint32_t smem_to_u32(const void* p) {
    uint32_t a;
    asm("{ .reg .u64 t; cvta.to.shared.u64 t, %1; cvt.u32.u64 %0, t; }" : "=r"(a) : "l"(p));
    return a;
}
#define LDSM4(R, addr) \
    asm volatile("ldmatrix.sync.aligned.m8n8.x4.shared.b16 {%0,%1,%2,%3}, [%4];" \
        : "=r"((R)[0]), "=r"((R)[1]), "=r"((R)[2]), "=r"((R)[3]) : "r"(addr))
#define LDSM2(R, addr) \
    asm volatile("ldmatrix.sync.aligned.m8n8.x2.shared.b16 {%0,%1}, [%2];" \
        : "=r"((R)[0]), "=r"((R)[1]) : "r"(addr))
#define CP16(smaddr, gptr) \
    asm volatile("cp.async.cg.shared.global [%0], [%1], 16;" \
        :: "r"((uint32_t)(smaddr)), "l"(gptr))
#define CP_COMMIT() asm volatile("cp.async.commit_group;" ::: "memory")
#define CP_WAIT1()  asm volatile("cp.async.wait_group 1;" ::: "memory")
#define CP_WAIT0()  asm volatile("cp.async.wait_group 0;" ::: "memory")

__device__ __forceinline__ void mma_fp16(float* c, const uint32_t* a, const uint32_t* b) {
    asm volatile("mma.sync.aligned.m16n8k16.row.col.f32.f16.f16.f32 "
        "{%0,%1,%2,%3}, {%4,%5,%6,%7}, {%8,%9}, {%0,%1,%2,%3};"
        : "+f"(c[0]), "+f"(c[1]), "+f"(c[2]), "+f"(c[3])
        : "r"(a[0]), "r"(a[1]), "r"(a[2]), "r"(a[3]), "r"(b[0]), "r"(b[1]));
}

__device__ __forceinline__ float fexp(float x) {
    float y = x * 1.4426950408889634f;
    y = fmaxf(y, -126.0f);
    float r = rintf(y);
    float t = (y - r) * 0.6931471805599453f;
    float p = 1.3888889e-3f;
    p = fmaf(p, t, 8.3333333e-3f);
    p = fmaf(p, t, 4.1666667e-2f);
    p = fmaf(p, t, 1.6666667e-1f);
    p = fmaf(p, t, 0.5f);
    p = fmaf(p, t, 1.0f);
    p = fmaf(p, t, 1.0f);
    float sc = __int_as_float(((int)r + 127) << 23);
    return p * sc;
}

// ---------------- feature -> fp16 ------------------------------------------
__global__ __launch_bounds__(256) void k_split(const float* __restrict__ X)
{
    int t = blockIdx.x * 256 + threadIdx.x;
    float4 v = *(const float4*)&X[t * 4];
    __half h[4];
    h[0] = __float2half_rn(v.x); h[1] = __float2half_rn(v.y);
    h[2] = __float2half_rn(v.z); h[3] = __float2half_rn(v.w);
    *(uint2*)&g_Fh[t * 4] = *(uint2*)h;
}

// ---------------- W transpose -> fp16 --------------------------------------
__global__ __launch_bounds__(256) void k_wsplit(const float* __restrict__ Wqk,
                                               const float* __restrict__ Wv)
{
    int n = blockIdx.x;
    int k = threadIdx.x;
    int sec = n >> 8, nn = n & 255;
    float w = (sec == 0) ? Wqk[k * 256 + nn]
            : (sec == 1) ? Wqk[65536 + k * 256 + nn]
                         : Wv[k * 256 + nn];
    g_Wth[n * 256 + k] = __float2half_rn(w);
}

// ---------------- shared MMA GEMM kernel (fp16 1-pass, cp.async 2-stage) ---
// mode 0: C[65536x768] = F @ Wt^T  -> scatter Q(fp16)/K/V (+bias)
// mode 1: C[65536x256] = Q @ bnT^T -> fp32 out
// mode 2: lam partials: C[256x256] = Pt @ Vt^T over 1024-seq split
#define ROWB 80
#define BUFB (128*ROWB)          // 10240 bytes per operand buffer
#define STAGEB (2*BUFB)          // 20480 bytes per stage (A, B)
#define SMEM_MMA (2*STAGEB)      // 40960 bytes

__global__ __launch_bounds__(256, 2) void k_mma(int mode, const float* __restrict__ bqk,
                                                const float* __restrict__ bv,
                                                float* __restrict__ outp)
{
    extern __shared__ __align__(16) unsigned char sm[];
    int tid = threadIdx.x, lane = tid & 31, wid = tid >> 5;
    int wm = wid >> 2, wn = wid & 3;

    const __half *Ah, *Bh;
    long astr, bstr;
    int m0, ncol0;
    int nk = (mode == 2) ? 32 : 8;
    if (mode == 0) {
        ncol0 = blockIdx.x * 128; m0 = blockIdx.y * 128;
        Ah = g_Fh + (long)m0 * 256;
        Bh = g_Wth + (long)ncol0 * 256;
        astr = bstr = 256;
    } else if (mode == 1) {
        ncol0 = blockIdx.x * 128; m0 = blockIdx.y * 128;
        int b = m0 >> 13;
        Ah = g_Qh + (long)m0 * 256;
        Bh = g_bnTh + (long)b * 65536 + (long)ncol0 * 256;
        astr = bstr = 256;
    } else {
        int e0 = blockIdx.x * 128, d0 = blockIdx.y * 128;
        int b = blockIdx.z >> 3, sp = blockIdx.z & 7;
        long ab = (long)(b * 256 + d0) * NN + sp * 1024;
        long bb = (long)(b * 256 + e0) * NN + sp * 1024;
        Ah = g_Pth + ab;
        Bh = g_Vth + bb;
        astr = bstr = NN;
        m0 = d0; ncol0 = e0;
    }

    float c[16][4];
    #pragma unroll
    for (int i = 0; i < 16; i++)
        #pragma unroll
        for (int j = 0; j < 4; j++) c[i][j] = 0.f;

    uint32_t smb = smem_to_u32(sm);
    int lrow0 = tid >> 2, lcc = tid & 3;
    int lrow1 = lrow0 + 64;

    auto load_chunk = [&](int kk, int st) {
        uint32_t sb = smb + st * STAGEB;
        #pragma unroll
        for (int buf = 0; buf < 2; buf++) {
            const __half* src = (buf == 0) ? Ah : Bh;
            long str = (buf == 0) ? astr : bstr;
            CP16(sb + buf * BUFB + lrow0 * ROWB + lcc * 16,
                 src + (long)lrow0 * str + kk + lcc * 8);
            CP16(sb + buf * BUFB + lrow1 * ROWB + lcc * 16,
                 src + (long)lrow1 * str + kk + lcc * 8);
        }
    };

    load_chunk(0, 0);
    CP_COMMIT();

    for (int ch = 0; ch < nk; ch++) {
        int cur = ch & 1;
        if (ch + 1 < nk) { load_chunk((ch + 1) * 32, cur ^ 1); CP_COMMIT(); }
        if (ch + 1 < nk) { CP_WAIT1(); } else { CP_WAIT0(); }
        __syncthreads();

        uint32_t sb = smb + cur * STAGEB;
        #pragma unroll
        for (int k0 = 0; k0 < 2; k0++) {
            uint32_t a[4][4], b_h[4][2];
            #pragma unroll
            for (int nt = 0; nt < 4; nt++) {
                uint32_t rb = sb + BUFB + (wn*32 + nt*8 + (lane & 7)) * ROWB
                            + (k0*16 + ((lane >> 3) & 1) * 8) * 2;
                LDSM2(b_h[nt], rb);
            }
            #pragma unroll
            for (int mt = 0; mt < 4; mt++) {
                uint32_t ra = sb + (wm*64 + mt*16 + (lane & 15)) * ROWB
                            + (k0*16 + (lane >> 4) * 8) * 2;
                LDSM4(a[mt], ra);
            }
            #pragma unroll
            for (int mt = 0; mt < 4; mt++)
                #pragma unroll
                for (int nt = 0; nt < 4; nt++)
                    mma_fp16(c[mt*4+nt], a[mt], b_h[nt]);
        }
        __syncthreads();
    }

    // epilogue
    int rbase = m0 + wm * 64;
    int cl0 = wn * 32;
    #pragma unroll
    for (int mt = 0; mt < 4; mt++) {
        #pragma unroll
        for (int nt = 0; nt < 4; nt++) {
            float* cc = c[mt*4+nt];
            int r0 = rbase + mt*16 + (lane >> 2);
            int cl = cl0 + nt*8 + (lane & 3)*2;
            if (mode == 1) {
                float2 v0 = {cc[0], cc[1]}, v1 = {cc[2], cc[3]};
                *(float2*)&outp[(long)r0 * 256 + ncol0 + cl] = v0;
                *(float2*)&outp[(long)(r0+8) * 256 + ncol0 + cl] = v1;
            } else if (mode == 2) {
                int sp = blockIdx.z & 7;
                int b = blockIdx.z >> 3;
                float* op = g_lampart + (long)sp * (BB*DD*DD) + (long)b * 65536;
                float2 v0 = {cc[0], cc[1]}, v1 = {cc[2], cc[3]};
                *(float2*)&op[(long)r0 * 256 + ncol0 + cl] = v0;
                *(float2*)&op[(long)(r0+8) * 256 + ncol0 + cl] = v1;
            } else {
                int sec = ncol0 >> 8;
                int cg = (ncol0 & 255) + cl;
                if (sec == 0) {
                    float b0 = bqk[cg], b1 = bqk[cg+1];
                    #pragma unroll
                    for (int hrow = 0; hrow < 2; hrow++) {
                        int r = r0 + hrow * 8;
                        __half h0 = __float2half_rn(cc[hrow*2+0] + b0);
                        __half h1 = __float2half_rn(cc[hrow*2+1] + b1);
                        __half2 ph; ph.x = h0; ph.y = h1;
                        *(__half2*)&g_Qh[(long)r*256 + cg] = ph;
                    }
                } else {
                    const float* bb = (sec == 1) ? bqk + 256 : bv;
                    float* dst = (sec == 1) ? g_K : g_V;
                    float b0 = bb[cg], b1 = bb[cg+1];
                    float2 v0 = {cc[0] + b0, cc[1] + b1};
                    float2 v1 = {cc[2] + b0, cc[3] + b1};
                    *(float2*)&dst[(long)r0 * 256 + cg] = v0;
                    *(float2*)&dst[(long)(r0+8) * 256 + cg] = v1;
                }
            }
        }
    }
}

// ---------------- softmax stats phase A: per-chunk exp-sums ----------------
__global__ __launch_bounds__(256) void k_stats1()
{
    int ch = blockIdx.x;
    int b  = blockIdx.y >> 3;
    int d0 = (blockIdx.y & 7) << 5;
    int dd = threadIdx.x & 31;
    int g  = threadIdx.x >> 5;
    int d  = d0 + dd;
    const float* base = g_K + ((long)b * NN + ch * 256) * 256 + d;

    float acc0 = 0.f, acc1 = 0.f, acc2 = 0.f, acc3 = 0.f;
    #pragma unroll 8
    for (int i = 0; i < 32; i += 4) {
        acc0 += fexp(base[(long)(g + (i+0)*8) * 256]);
        acc1 += fexp(base[(long)(g + (i+1)*8) * 256]);
        acc2 += fexp(base[(long)(g + (i+2)*8) * 256]);
        acc3 += fexp(base[(long)(g + (i+3)*8) * 256]);
    }
    float s = (acc0 + acc1) + (acc2 + acc3);
    __shared__ float ss[8][32];
    ss[g][dd] = s;
    __syncthreads();
    if (g == 0) {
        float S = ss[0][dd];
        #pragma unroll
        for (int i = 1; i < 8; i++) S += ss[i][dd];
        g_psum[ch * (BB*DD) + b * 256 + d] = S;
    }
}

// ---------------- phase B: combine chunk sums ------------------------------
__global__ __launch_bounds__(256) void k_stats2()
{
    int t = blockIdx.x * 256 + threadIdx.x;
    if (t >= BB*DD) return;
    float S = 0.f;
    #pragma unroll
    for (int i = 0; i < NCHUNK; i++) S += g_psum[i * (BB*DD) + t];
    g_colrcp[t] = PSCALE / S;          // P stored scaled by PSCALE
}

// ---------------- fused P/V transpose --------------------------------------
// z: 0..7 = P path (exp-normalize*PSCALE), 8..15 = V path
__global__ __launch_bounds__(256) void k_pvT()
{
    __shared__ float tile[64][33];
    int which = blockIdx.z >> 3;
    int b = blockIdx.z & 7, d0 = blockIdx.y * 32, n0 = blockIdx.x * 64;
    int lx = threadIdx.x & 31, ly = threadIdx.x >> 5;
    if (which == 0) {
        float rc = g_colrcp[b * 256 + d0 + lx];
        #pragma unroll
        for (int i = 0; i < 8; i++) {
            int n = ly + i * 8;
            float kv = g_K[((long)b * NN + n0 + n) * 256 + d0 + lx];
            tile[n][lx] = fexp(kv) * rc;
        }
    } else {
        #pragma unroll
        for (int i = 0; i < 8; i++) {
            int n = ly + i * 8;
            tile[n][lx] = g_V[((long)b * NN + n0 + n) * 256 + d0 + lx];
        }
    }
    __syncthreads();
    int sx = threadIdx.x & 63, sy = threadIdx.x >> 6;
    __half* dh = (which == 0) ? g_Pth : g_Vth;
    #pragma unroll
    for (int j = 0; j < 8; j++) {
        int dl_i = sy + j * 4;
        long o = (long)(b * 256 + d0 + dl_i) * NN + n0 + sx;
        dh[o] = __float2half_rn(tile[sx][dl_i]);
    }
}

// ---------------- fused reduce split-K + BN stats (per d, scale-aware) -----
__global__ __launch_bounds__(256) void k_redstat(const float* __restrict__ gamma,
                                                const float* __restrict__ beta)
{
    int d = blockIdx.x;
    int tid = threadIdx.x;
    float sum = 0.f, sq = 0.f;
    #pragma unroll
    for (int i = 0; i < 8; i++) {
        int f = tid + i * 256;       // 0..2047 -> (b, e)
        int b = f >> 8, e = f & 255;
        long idx = ((long)(b * 256 + d)) * 256 + e;
        float v = 0.f;
        #pragma unroll
        for (int s = 0; s < NSPLIT; s++)
            v += g_lampart[(long)s * (BB*DD*DD) + idx];
        g_lam[idx] = v;              // scaled lam' = PSCALE * lam
        sum += v; sq = fmaf(v, v, sq);
    }
    __shared__ float s1[256], s2[256];
    s1[tid] = sum; s2[tid] = sq;
    __syncthreads();
    for (int st = 128; st > 0; st >>= 1) {
        if (tid < st) { s1[tid] += s1[tid+st]; s2[tid] += s2[tid+st]; }
        __syncthreads();
    }
    if (tid == 0) {
        float mean_p = s1[0] * (1.0f / 2048.0f);            // scaled mean
        float var_p  = s2[0] * (1.0f / 2048.0f) - mean_p * mean_p;
        float mean_u = mean_p * PSCALE_INV;                 // true lam domain
        float var_u  = var_p * (PSCALE_INV * PSCALE_INV);
        float rstd = rsqrtf(var_u + 1e-5f);
        float gg = gamma[d];
        g_scale[d] = rstd * gg * PSCALE_INV;                // applied to lam'
        g_shift[d] = beta[d] - mean_u * rstd * gg;
    }
}

// ---------------- bnT = transpose(BN(lam')), fp16 --------------------------
__global__ void k_bnT()
{
    __shared__ float tile[32][33];
    int b = blockIdx.z, dt = blockIdx.y * 32, et = blockIdx.x * 32;
    int tx = threadIdx.x, ty = threadIdx.y;
    #pragma unroll
    for (int i = 0; i < 4; i++) {
        int d = dt + ty + i * 8;
        float sc = g_scale[d], sh = g_shift[d];
        tile[ty + i * 8][tx] = fmaf(g_lam[(b * 256 + d) * 256 + et + tx], sc, sh);
    }
    __syncthreads();
    #pragma unroll
    for (int i = 0; i < 4; i++) {
        int e = et + ty + i * 8;
        float v = tile[tx][ty + i * 8];
        int o = (b * 256 + e) * 256 + dt + tx;
        g_bnTh[o] = __float2half_rn(v);
    }
}

// ---------------- launch ---------------------------------------------------
extern "C" void kernel_launch(void* const* d_in, const int* in_sizes, int n_in,
                              void* d_out, int out_size)
{
    const float* feature = (const float*)d_in[0];
    const float* W_qk    = (const float*)d_in[1];
    const float* b_qk    = (const float*)d_in[2];
    const float* W_v     = (const float*)d_in[3];
    const float* b_v     = (const float*)d_in[4];
    const float* gamma   = (const float*)d_in[5];
    const float* beta    = (const float*)d_in[6];
    float* out = (float*)d_out;

    cudaFuncSetAttribute(k_mma, cudaFuncAttributeMaxDynamicSharedMemorySize,
                         SMEM_MMA);

    k_split<<<16384, 256>>>(feature);
    k_wsplit<<<768, 256>>>(W_qk, W_v);
    k_mma<<<dim3(6, 512), 256, SMEM_MMA>>>(0, b_qk, b_v, nullptr);      // QKV
    k_stats1<<<dim3(NCHUNK, 64), 256>>>();
    k_stats2<<<8, 256>>>();
    k_pvT<<<dim3(128, 8, 16), 256>>>();                                 // Pt + Vt
    k_mma<<<dim3(2, 2, BB*NSPLIT), 256, SMEM_MMA>>>(2, nullptr, nullptr, nullptr);
    k_redstat<<<256, 256>>>(gamma, beta);
    k_bnT<<<dim3(8, 8, 8), dim3(32, 8)>>>();
    k_mma<<<dim3(2, 512), 256, SMEM_MMA>>>(1, nullptr, nullptr, out);   // out
}

// round 17
// speedup vs baseline: 3.1971x; 1.0236x over previous
#include <cuda_runtime.h>
#include <cuda_fp16.h>
#include <cstdint>

#define BB 8
#define NN 8192
#define DD 256
#define NSPLIT 8
#define NCHUNK 32          // k_stats row chunks (8192/256)
#define TOTROWS (BB*NN)    // 65536
#define PSCALE 2048.0f
#define PSCALE_INV (1.0f/2048.0f)

// ---------------- scratch globals ------------------------------------------
__device__ __half g_Kh[TOTROWS*DD];               // K logits fp16 row-major
__device__ __half g_Vh[TOTROWS*DD];               // V fp16 row-major
__device__ __half g_Fh[TOTROWS*DD];               // feature fp16
__device__ __half g_Qh[TOTROWS*DD];               // Q fp16
__device__ __half g_Wth[768*DD];                  // W transposed fp16
__device__ __half g_Pth[BB*DD*NN];                // P*2048 transposed [b][d][n]
__device__ __half g_Vth[BB*DD*NN];                // V transposed [b][e][n]
__device__ __half g_bnTh[BB*DD*DD];               // bn transposed [b][e][d]
__device__ float g_psum[NCHUNK*BB*DD];
__device__ float g_colrcp[BB*DD];
__device__ float g_lampart[NSPLIT*BB*DD*DD];      // scaled by PSCALE
__device__ float g_lam[BB*DD*DD];                 // scaled by PSCALE
__device__ float g_scale[DD];
__device__ float g_shift[DD];

// ---------------- helpers --------------------------------------------------
__device__ __forceinline__ uint32_t smem_to_u32(const void* p) {
    uint32_t a;
    asm("{ .reg .u64 t; cvta.to.shared.u64 t, %1; cvt.u32.u64 %0, t; }" : "=r"(a) : "l"(p));
    return a;
}
#define LDSM4(R, addr) \
    asm volatile("ldmatrix.sync.aligned.m8n8.x4.shared.b16 {%0,%1,%2,%3}, [%4];" \
        : "=r"((R)[0]), "=r"((R)[1]), "=r"((R)[2]), "=r"((R)[3]) : "r"(addr))
#define LDSM2(R, addr) \
    asm volatile("ldmatrix.sync.aligned.m8n8.x2.shared.b16 {%0,%1}, [%2];" \
        : "=r"((R)[0]), "=r"((R)[1]) : "r"(addr))
#define CP16(smaddr, gptr) \
    asm volatile("cp.async.cg.shared.global [%0], [%1], 16;" \
        :: "r"((uint32_t)(smaddr)), "l"(gptr))
#define CP_COMMIT() asm volatile("cp.async.commit_group;" ::: "memory")
#define CP_WAIT1()  asm volatile("cp.async.wait_group 1;" ::: "memory")
#define CP_WAIT0()  asm volatile("cp.async.wait_group 0;" ::: "memory")

__device__ __forceinline__ void mma_fp16(float* c, const uint32_t* a, const uint32_t* b) {
    asm volatile("mma.sync.aligned.m16n8k16.row.col.f32.f16.f16.f32 "
        "{%0,%1,%2,%3}, {%4,%5,%6,%7}, {%8,%9}, {%0,%1,%2,%3};"
        : "+f"(c[0]), "+f"(c[1]), "+f"(c[2]), "+f"(c[3])
        : "r"(a[0]), "r"(a[1]), "r"(a[2]), "r"(a[3]), "r"(b[0]), "r"(b[1]));
}

__device__ __forceinline__ float fexp(float x) {
    float y = x * 1.4426950408889634f;
    y = fmaxf(y, -126.0f);
    float r = rintf(y);
    float t = (y - r) * 0.6931471805599453f;
    float p = 1.3888889e-3f;
    p = fmaf(p, t, 8.3333333e-3f);
    p = fmaf(p, t, 4.1666667e-2f);
    p = fmaf(p, t, 1.6666667e-1f);
    p = fmaf(p, t, 0.5f);
    p = fmaf(p, t, 1.0f);
    p = fmaf(p, t, 1.0f);
    float sc = __int_as_float(((int)r + 127) << 23);
    return p * sc;
}

// ---------------- feature -> fp16 ------------------------------------------
__global__ __launch_bounds__(256) void k_split(const float* __restrict__ X)
{
    int t = blockIdx.x * 256 + threadIdx.x;
    float4 v = *(const float4*)&X[t * 4];
    __half h[4];
    h[0] = __float2half_rn(v.x); h[1] = __float2half_rn(v.y);
    h[2] = __float2half_rn(v.z); h[3] = __float2half_rn(v.w);
    *(uint2*)&g_Fh[t * 4] = *(uint2*)h;
}

// ---------------- W transpose -> fp16 --------------------------------------
__global__ __launch_bounds__(256) void k_wsplit(const float* __restrict__ Wqk,
                                               const float* __restrict__ Wv)
{
    int n = blockIdx.x;
    int k = threadIdx.x;
    int sec = n >> 8, nn = n & 255;
    float w = (sec == 0) ? Wqk[k * 256 + nn]
            : (sec == 1) ? Wqk[65536 + k * 256 + nn]
                         : Wv[k * 256 + nn];
    g_Wth[n * 256 + k] = __float2half_rn(w);
}

// ---------------- shared MMA GEMM kernel (fp16 1-pass, cp.async 2-stage) ---
// mode 0: C[65536x768] = F @ Wt^T  -> scatter Q/K/V fp16 (+bias)
// mode 1: C[65536x256] = Q @ bnT^T -> fp32 out
// mode 2: lam partials: C[256x256] = Pt @ Vt^T over 1024-seq split
#define ROWB 80
#define BUFB (128*ROWB)          // 10240 bytes per operand buffer
#define STAGEB (2*BUFB)          // 20480 bytes per stage (A, B)
#define SMEM_MMA (2*STAGEB)      // 40960 bytes

__global__ __launch_bounds__(256, 2) void k_mma(int mode, const float* __restrict__ bqk,
                                                const float* __restrict__ bv,
                                                float* __restrict__ outp)
{
    extern __shared__ __align__(16) unsigned char sm[];
    int tid = threadIdx.x, lane = tid & 31, wid = tid >> 5;
    int wm = wid >> 2, wn = wid & 3;

    const __half *Ah, *Bh;
    long astr, bstr;
    int m0, ncol0;
    int nk = (mode == 2) ? 32 : 8;
    if (mode == 0) {
        ncol0 = blockIdx.x * 128; m0 = blockIdx.y * 128;
        Ah = g_Fh + (long)m0 * 256;
        Bh = g_Wth + (long)ncol0 * 256;
        astr = bstr = 256;
    } else if (mode == 1) {
        ncol0 = blockIdx.x * 128; m0 = blockIdx.y * 128;
        int b = m0 >> 13;
        Ah = g_Qh + (long)m0 * 256;
        Bh = g_bnTh + (long)b * 65536 + (long)ncol0 * 256;
        astr = bstr = 256;
    } else {
        int e0 = blockIdx.x * 128, d0 = blockIdx.y * 128;
        int b = blockIdx.z >> 3, sp = blockIdx.z & 7;
        long ab = (long)(b * 256 + d0) * NN + sp * 1024;
        long bb = (long)(b * 256 + e0) * NN + sp * 1024;
        Ah = g_Pth + ab;
        Bh = g_Vth + bb;
        astr = bstr = NN;
        m0 = d0; ncol0 = e0;
    }

    float c[16][4];
    #pragma unroll
    for (int i = 0; i < 16; i++)
        #pragma unroll
        for (int j = 0; j < 4; j++) c[i][j] = 0.f;

    uint32_t smb = smem_to_u32(sm);
    int lrow0 = tid >> 2, lcc = tid & 3;
    int lrow1 = lrow0 + 64;

    auto load_chunk = [&](int kk, int st) {
        uint32_t sb = smb + st * STAGEB;
        #pragma unroll
        for (int buf = 0; buf < 2; buf++) {
            const __half* src = (buf == 0) ? Ah : Bh;
            long str = (buf == 0) ? astr : bstr;
            CP16(sb + buf * BUFB + lrow0 * ROWB + lcc * 16,
                 src + (long)lrow0 * str + kk + lcc * 8);
            CP16(sb + buf * BUFB + lrow1 * ROWB + lcc * 16,
                 src + (long)lrow1 * str + kk + lcc * 8);
        }
    };

    load_chunk(0, 0);
    CP_COMMIT();

    for (int ch = 0; ch < nk; ch++) {
        int cur = ch & 1;
        if (ch + 1 < nk) { load_chunk((ch + 1) * 32, cur ^ 1); CP_COMMIT(); }
        if (ch + 1 < nk) { CP_WAIT1(); } else { CP_WAIT0(); }
        __syncthreads();

        uint32_t sb = smb + cur * STAGEB;
        #pragma unroll
        for (int k0 = 0; k0 < 2; k0++) {
            uint32_t a[4][4], b_h[4][2];
            #pragma unroll
            for (int nt = 0; nt < 4; nt++) {
                uint32_t rb = sb + BUFB + (wn*32 + nt*8 + (lane & 7)) * ROWB
                            + (k0*16 + ((lane >> 3) & 1) * 8) * 2;
                LDSM2(b_h[nt], rb);
            }
            #pragma unroll
            for (int mt = 0; mt < 4; mt++) {
                uint32_t ra = sb + (wm*64 + mt*16 + (lane & 15)) * ROWB
                            + (k0*16 + (lane >> 4) * 8) * 2;
                LDSM4(a[mt], ra);
            }
            #pragma unroll
            for (int mt = 0; mt < 4; mt++)
                #pragma unroll
                for (int nt = 0; nt < 4; nt++)
                    mma_fp16(c[mt*4+nt], a[mt], b_h[nt]);
        }
        __syncthreads();
    }

    // epilogue
    int rbase = m0 + wm * 64;
    int cl0 = wn * 32;
    #pragma unroll
    for (int mt = 0; mt < 4; mt++) {
        #pragma unroll
        for (int nt = 0; nt < 4; nt++) {
            float* cc = c[mt*4+nt];
            int r0 = rbase + mt*16 + (lane >> 2);
            int cl = cl0 + nt*8 + (lane & 3)*2;
            if (mode == 1) {
                float2 v0 = {cc[0], cc[1]}, v1 = {cc[2], cc[3]};
                *(float2*)&outp[(long)r0 * 256 + ncol0 + cl] = v0;
                *(float2*)&outp[(long)(r0+8) * 256 + ncol0 + cl] = v1;
            } else if (mode == 2) {
                int sp = blockIdx.z & 7;
                int b = blockIdx.z >> 3;
                float* op = g_lampart + (long)sp * (BB*DD*DD) + (long)b * 65536;
                float2 v0 = {cc[0], cc[1]}, v1 = {cc[2], cc[3]};
                *(float2*)&op[(long)r0 * 256 + ncol0 + cl] = v0;
                *(float2*)&op[(long)(r0+8) * 256 + ncol0 + cl] = v1;
            } else {
                int sec = ncol0 >> 8;
                int cg = (ncol0 & 255) + cl;
                const float* bb = (sec == 0) ? bqk : (sec == 1) ? bqk + 256 : bv;
                __half* dst = (sec == 0) ? g_Qh : (sec == 1) ? g_Kh : g_Vh;
                float b0 = bb[cg], b1 = bb[cg+1];
                #pragma unroll
                for (int hrow = 0; hrow < 2; hrow++) {
                    int r = r0 + hrow * 8;
                    __half h0 = __float2half_rn(cc[hrow*2+0] + b0);
                    __half h1 = __float2half_rn(cc[hrow*2+1] + b1);
                    __half2 ph; ph.x = h0; ph.y = h1;
                    *(__half2*)&dst[(long)r*256 + cg] = ph;
                }
            }
        }
    }
}

// ---------------- softmax stats phase A: per-chunk exp-sums (fp16 K) -------
__global__ __launch_bounds__(256) void k_stats1()
{
    int ch = blockIdx.x;
    int b  = blockIdx.y >> 3;
    int d0 = (blockIdx.y & 7) << 5;
    int dd = threadIdx.x & 31;
    int g  = threadIdx.x >> 5;
    int d  = d0 + dd;
    const __half* base = g_Kh + ((long)b * NN + ch * 256) * 256 + d;

    float acc0 = 0.f, acc1 = 0.f, acc2 = 0.f, acc3 = 0.f;
    #pragma unroll 8
    for (int i = 0; i < 32; i += 4) {
        acc0 += fexp(__half2float(base[(long)(g + (i+0)*8) * 256]));
        acc1 += fexp(__half2float(base[(long)(g + (i+1)*8) * 256]));
        acc2 += fexp(__half2float(base[(long)(g + (i+2)*8) * 256]));
        acc3 += fexp(__half2float(base[(long)(g + (i+3)*8) * 256]));
    }
    float s = (acc0 + acc1) + (acc2 + acc3);
    __shared__ float ss[8][32];
    ss[g][dd] = s;
    __syncthreads();
    if (g == 0) {
        float S = ss[0][dd];
        #pragma unroll
        for (int i = 1; i < 8; i++) S += ss[i][dd];
        g_psum[ch * (BB*DD) + b * 256 + d] = S;
    }
}

// ---------------- phase B: combine chunk sums ------------------------------
__global__ __launch_bounds__(256) void k_stats2()
{
    int t = blockIdx.x * 256 + threadIdx.x;
    if (t >= BB*DD) return;
    float S = 0.f;
    #pragma unroll
    for (int i = 0; i < NCHUNK; i++) S += g_psum[i * (BB*DD) + t];
    g_colrcp[t] = PSCALE / S;          // P stored scaled by PSCALE
}

// ---------------- fused P/V transpose (fp16 inputs) ------------------------
// z: 0..7 = P path (exp-normalize*PSCALE), 8..15 = V path
__global__ __launch_bounds__(256) void k_pvT()
{
    __shared__ float tile[64][33];
    int which = blockIdx.z >> 3;
    int b = blockIdx.z & 7, d0 = blockIdx.y * 32, n0 = blockIdx.x * 64;
    int lx = threadIdx.x & 31, ly = threadIdx.x >> 5;
    if (which == 0) {
        float rc = g_colrcp[b * 256 + d0 + lx];
        #pragma unroll
        for (int i = 0; i < 8; i++) {
            int n = ly + i * 8;
            float kv = __half2float(g_Kh[((long)b * NN + n0 + n) * 256 + d0 + lx]);
            tile[n][lx] = fexp(kv) * rc;
        }
    } else {
        #pragma unroll
        for (int i = 0; i < 8; i++) {
            int n = ly + i * 8;
            tile[n][lx] = __half2float(g_Vh[((long)b * NN + n0 + n) * 256 + d0 + lx]);
        }
    }
    __syncthreads();
    int sx = threadIdx.x & 63, sy = threadIdx.x >> 6;
    __half* dh = (which == 0) ? g_Pth : g_Vth;
    #pragma unroll
    for (int j = 0; j < 8; j++) {
        int dl_i = sy + j * 4;
        long o = (long)(b * 256 + d0 + dl_i) * NN + n0 + sx;
        dh[o] = __float2half_rn(tile[sx][dl_i]);
    }
}

// ---------------- fused reduce split-K + BN stats (per d, scale-aware) -----
__global__ __launch_bounds__(256) void k_redstat(const float* __restrict__ gamma,
                                                const float* __restrict__ beta)
{
    int d = blockIdx.x;
    int tid = threadIdx.x;
    float sum = 0.f, sq = 0.f;
    #pragma unroll
    for (int i = 0; i < 8; i++) {
        int f = tid + i * 256;       // 0..2047 -> (b, e)
        int b = f >> 8, e = f & 255;
        long idx = ((long)(b * 256 + d)) * 256 + e;
        float v = 0.f;
        #pragma unroll
        for (int s = 0; s < NSPLIT; s++)
            v += g_lampart[(long)s * (BB*DD*DD) + idx];
        g_lam[idx] = v;              // scaled lam' = PSCALE * lam
        sum += v; sq = fmaf(v, v, sq);
    }
    __shared__ float s1[256], s2[256];
    s1[tid] = sum; s2[tid] = sq;
    __syncthreads();
    for (int st = 128; st > 0; st >>= 1) {
        if (tid < st) { s1[tid] += s1[tid+st]; s2[tid] += s2[tid+st]; }
        __syncthreads();
    }
    if (tid == 0) {
        float mean_p = s1[0] * (1.0f / 2048.0f);            // scaled mean
        float var_p  = s2[0] * (1.0f / 2048.0f) - mean_p * mean_p;
        float mean_u = mean_p * PSCALE_INV;                 // true lam domain
        float var_u  = var_p * (PSCALE_INV * PSCALE_INV);
        float rstd = rsqrtf(var_u + 1e-5f);
        float gg = gamma[d];
        g_scale[d] = rstd * gg * PSCALE_INV;                // applied to lam'
        g_shift[d] = beta[d] - mean_u * rstd * gg;
    }
}

// ---------------- bnT = transpose(BN(lam')), fp16 --------------------------
__global__ void k_bnT()
{
    __shared__ float tile[32][33];
    int b = blockIdx.z, dt = blockIdx.y * 32, et = blockIdx.x * 32;
    int tx = threadIdx.x, ty = threadIdx.y;
    #pragma unroll
    for (int i = 0; i < 4; i++) {
        int d = dt + ty + i * 8;
        float sc = g_scale[d], sh = g_shift[d];
        tile[ty + i * 8][tx] = fmaf(g_lam[(b * 256 + d) * 256 + et + tx], sc, sh);
    }
    __syncthreads();
    #pragma unroll
    for (int i = 0; i < 4; i++) {
        int e = et + ty + i * 8;
        float v = tile[tx][ty + i * 8];
        int o = (b * 256 + e) * 256 + dt + tx;
        g_bnTh[o] = __float2half_rn(v);
    }
}

// ---------------- launch ---------------------------------------------------
extern "C" void kernel_launch(void* const* d_in, const int* in_sizes, int n_in,
                              void* d_out, int out_size)
{
    const float* feature = (const float*)d_in[0];
    const float* W_qk    = (const float*)d_in[1];
    const float* b_qk    = (const float*)d_in[2];
    const float* W_v     = (const float*)d_in[3];
    const float* b_v     = (const float*)d_in[4];
    const float* gamma   = (const float*)d_in[5];
    const float* beta    = (const float*)d_in[6];
    float* out = (float*)d_out;

    cudaFuncSetAttribute(k_mma, cudaFuncAttributeMaxDynamicSharedMemorySize,
                         SMEM_MMA);

    k_split<<<16384, 256>>>(feature);
    k_wsplit<<<768, 256>>>(W_qk, W_v);
    k_mma<<<dim3(6, 512), 256, SMEM_MMA>>>(0, b_qk, b_v, nullptr);      // QKV
    k_stats1<<<dim3(NCHUNK, 64), 256>>>();
    k_stats2<<<8, 256>>>();
    k_pvT<<<dim3(128, 8, 16), 256>>>();                                 // Pt + Vt
    k_mma<<<dim3(2, 2, BB*NSPLIT), 256, SMEM_MMA>>>(2, nullptr, nullptr, nullptr);
    k_redstat<<<256, 256>>>(gamma, beta);
    k_bnT<<<dim3(8, 8, 8), dim3(32, 8)>>>();
    k_mma<<<dim3(2, 512), 256, SMEM_MMA>>>(1, nullptr, nullptr, out);   // out
}